// round 1
// baseline (speedup 1.0000x reference)
#include <cuda_runtime.h>

#define NU 100000
#define NT 100000
#define NN 200000
#define NE 600000

// ---- scratch (device globals; no runtime allocation) ----
__device__ float g_bufA[(size_t)NN * 128];
__device__ float g_bufB[(size_t)NN * 128];
__device__ float g_agg[(size_t)2 * NN * 128];
__device__ float g_cnt[2 * NN];
__device__ float g_inv[2 * NN];

__device__ __forceinline__ float lrelu(float x) { return x > 0.f ? x : 0.01f * x; }

// ---------------------------------------------------------------------------
// Input feature MLPs: users = [des->64 | num->32 | cat->32], tweets = tweet->128
// blockDim (128,2): threadIdx.x = output col, 2 rows per block
// ---------------------------------------------------------------------------
__global__ void feat_kernel(const float* __restrict__ des, const float* __restrict__ tweet,
                            const float* __restrict__ nump, const float* __restrict__ catp,
                            const float* __restrict__ Wd, const float* __restrict__ bd,
                            const float* __restrict__ Wn, const float* __restrict__ bn,
                            const float* __restrict__ Wc, const float* __restrict__ bc,
                            const float* __restrict__ Wt, const float* __restrict__ bt,
                            float* __restrict__ out) {
    int row = blockIdx.x * 2 + threadIdx.y;
    int o = threadIdx.x;
    if (row >= NN) return;
    float acc;
    if (row < NU) {
        if (o < 64) {
            acc = bd[o];
            const float* w = Wd + o * 100;
            const float* a = des + (size_t)row * 100;
#pragma unroll 4
            for (int k = 0; k < 100; k++) acc += a[k] * w[k];
        } else if (o < 96) {
            int oo = o - 64;
            acc = bn[oo];
            const float* w = Wn + oo * 6;
            const float* a = nump + (size_t)row * 6;
#pragma unroll
            for (int k = 0; k < 6; k++) acc += a[k] * w[k];
        } else {
            int oo = o - 96;
            acc = bc[oo];
            const float* w = Wc + oo * 11;
            const float* a = catp + (size_t)row * 11;
#pragma unroll
            for (int k = 0; k < 11; k++) acc += a[k] * w[k];
        }
    } else {
        int tr = row - NU;
        acc = bt[o];
        const float* w = Wt + o * 100;
        const float* a = tweet + (size_t)tr * 100;
#pragma unroll 4
        for (int k = 0; k < 100; k++) acc += a[k] * w[k];
    }
    out[(size_t)row * 128 + o] = lrelu(acc);
}

// ---------------------------------------------------------------------------
// SGEMM: C[M,128] = act(A[M,128] @ op(B) + bias)
// TRANSB=1: op(B)(k,n) = B[n*128+k]  (torch Linear W[out,in])
// BM=128, BN=128, BK=8, 256 threads, 8x8 per thread (split 4+4 for LDS.128)
// ---------------------------------------------------------------------------
template <int TRANSB, int RELU>
__global__ void __launch_bounds__(256) gemm_lin_kernel(const float* __restrict__ A,
                                                       const float* __restrict__ B,
                                                       const float* __restrict__ bias,
                                                       float* __restrict__ C, int M) {
    __shared__ float As[8][128];
    __shared__ float Bs[8][128];
    int tid = threadIdx.x;
    int tx = tid & 15, ty = tid >> 4;
    int rowBlock = blockIdx.x * 128;
    float acc[8][8];
#pragma unroll
    for (int i = 0; i < 8; i++)
#pragma unroll
        for (int j = 0; j < 8; j++) acc[i][j] = 0.f;

    int lr = tid >> 1, lk = (tid & 1) * 4;
    int grow = rowBlock + lr;

    for (int k0 = 0; k0 < 128; k0 += 8) {
        float4 av = make_float4(0.f, 0.f, 0.f, 0.f);
        if (grow < M) av = *(const float4*)(A + (size_t)grow * 128 + k0 + lk);
        As[lk + 0][lr] = av.x;
        As[lk + 1][lr] = av.y;
        As[lk + 2][lr] = av.z;
        As[lk + 3][lr] = av.w;
        if (TRANSB) {
            int e = tid * 4;
            int k = e >> 7, n = e & 127;
#pragma unroll
            for (int j = 0; j < 4; j++) Bs[k][n + j] = B[(size_t)(n + j) * 128 + k0 + k];
        } else {
            int k = tid >> 5, n4 = (tid & 31) * 4;
            *(float4*)&Bs[k][n4] = *(const float4*)(B + (size_t)(k0 + k) * 128 + n4);
        }
        __syncthreads();
#pragma unroll
        for (int kk = 0; kk < 8; kk++) {
            float4 a0 = *(const float4*)&As[kk][ty * 4];
            float4 a1 = *(const float4*)&As[kk][64 + ty * 4];
            float4 b0 = *(const float4*)&Bs[kk][tx * 4];
            float4 b1 = *(const float4*)&Bs[kk][64 + tx * 4];
            float ar[8] = {a0.x, a0.y, a0.z, a0.w, a1.x, a1.y, a1.z, a1.w};
            float br[8] = {b0.x, b0.y, b0.z, b0.w, b1.x, b1.y, b1.z, b1.w};
#pragma unroll
            for (int i = 0; i < 8; i++)
#pragma unroll
                for (int j = 0; j < 8; j++) acc[i][j] += ar[i] * br[j];
        }
        __syncthreads();
    }
#pragma unroll
    for (int i = 0; i < 8; i++) {
        int r = rowBlock + ((i < 4) ? ty * 4 + i : 64 + ty * 4 + i - 4);
        if (r < M) {
#pragma unroll
            for (int jh = 0; jh < 2; jh++) {
                int cb = jh * 64 + tx * 4;
                float4 v;
                v.x = acc[i][jh * 4 + 0] + bias[cb + 0];
                v.y = acc[i][jh * 4 + 1] + bias[cb + 1];
                v.z = acc[i][jh * 4 + 2] + bias[cb + 2];
                v.w = acc[i][jh * 4 + 3] + bias[cb + 3];
                if (RELU) {
                    v.x = lrelu(v.x); v.y = lrelu(v.y); v.z = lrelu(v.z); v.w = lrelu(v.w);
                }
                *(float4*)&C[(size_t)r * 128 + cb] = v;
            }
        }
    }
}

// ---------------------------------------------------------------------------
// RGCN conv GEMM: C = X@root + (agg0*inv0)@W0 + (agg1*inv1)@W1 + bias
// 3 K-segments of 128; per-row 1/deg scaling fused into A-tile load.
// ---------------------------------------------------------------------------
__global__ void __launch_bounds__(256) gemm_conv_kernel(const float* __restrict__ X,
                                                        const float* __restrict__ Agg,
                                                        const float* __restrict__ Inv,
                                                        const float* __restrict__ root,
                                                        const float* __restrict__ Wrel,
                                                        const float* __restrict__ bias,
                                                        float* __restrict__ C, int M) {
    __shared__ float As[8][128];
    __shared__ float Bs[8][128];
    int tid = threadIdx.x;
    int tx = tid & 15, ty = tid >> 4;
    int rowBlock = blockIdx.x * 128;
    float acc[8][8];
#pragma unroll
    for (int i = 0; i < 8; i++)
#pragma unroll
        for (int j = 0; j < 8; j++) acc[i][j] = 0.f;

    int lr = tid >> 1, lk = (tid & 1) * 4;
    int grow = rowBlock + lr;

    for (int seg = 0; seg < 3; seg++) {
        const float* Ap = (seg == 0) ? X : Agg + (size_t)(seg - 1) * NN * 128;
        const float* Bp = (seg == 0) ? root : Wrel + (size_t)(seg - 1) * 128 * 128;
        float s = 1.f;
        if (seg > 0 && grow < M) s = Inv[(size_t)(seg - 1) * NN + grow];
        for (int k0 = 0; k0 < 128; k0 += 8) {
            float4 av = make_float4(0.f, 0.f, 0.f, 0.f);
            if (grow < M) {
                av = *(const float4*)(Ap + (size_t)grow * 128 + k0 + lk);
                av.x *= s; av.y *= s; av.z *= s; av.w *= s;
            }
            As[lk + 0][lr] = av.x;
            As[lk + 1][lr] = av.y;
            As[lk + 2][lr] = av.z;
            As[lk + 3][lr] = av.w;
            {
                int k = tid >> 5, n4 = (tid & 31) * 4;
                *(float4*)&Bs[k][n4] = *(const float4*)(Bp + (size_t)(k0 + k) * 128 + n4);
            }
            __syncthreads();
#pragma unroll
            for (int kk = 0; kk < 8; kk++) {
                float4 a0 = *(const float4*)&As[kk][ty * 4];
                float4 a1 = *(const float4*)&As[kk][64 + ty * 4];
                float4 b0 = *(const float4*)&Bs[kk][tx * 4];
                float4 b1 = *(const float4*)&Bs[kk][64 + tx * 4];
                float ar[8] = {a0.x, a0.y, a0.z, a0.w, a1.x, a1.y, a1.z, a1.w};
                float br[8] = {b0.x, b0.y, b0.z, b0.w, b1.x, b1.y, b1.z, b1.w};
#pragma unroll
                for (int i = 0; i < 8; i++)
#pragma unroll
                    for (int j = 0; j < 8; j++) acc[i][j] += ar[i] * br[j];
            }
            __syncthreads();
        }
    }
#pragma unroll
    for (int i = 0; i < 8; i++) {
        int r = rowBlock + ((i < 4) ? ty * 4 + i : 64 + ty * 4 + i - 4);
        if (r < M) {
#pragma unroll
            for (int jh = 0; jh < 2; jh++) {
                int cb = jh * 64 + tx * 4;
                float4 v;
                v.x = acc[i][jh * 4 + 0] + bias[cb + 0];
                v.y = acc[i][jh * 4 + 1] + bias[cb + 1];
                v.z = acc[i][jh * 4 + 2] + bias[cb + 2];
                v.w = acc[i][jh * 4 + 3] + bias[cb + 3];
                *(float4*)&C[(size_t)r * 128 + cb] = v;
            }
        }
    }
}

// ---------------------------------------------------------------------------
// Edge scatter: one warp per edge, float4 vector atomics (sm_90+)
// ---------------------------------------------------------------------------
__global__ void scatter_kernel(const float* __restrict__ X, const int* __restrict__ ei,
                               const int* __restrict__ et, float* __restrict__ Agg) {
    int w = (blockIdx.x * blockDim.x + threadIdx.x) >> 5;
    int lane = threadIdx.x & 31;
    if (w >= NE) return;
    int src = ei[w];
    int dst = ei[NE + w];
    int r = et[w];
    float4 v = *(const float4*)(X + (size_t)src * 128 + lane * 4);
    atomicAdd((float4*)(Agg + ((size_t)r * NN + dst) * 128 + lane * 4), v);
}

__global__ void count_kernel(const int* __restrict__ ei, const int* __restrict__ et,
                             float* __restrict__ cnt) {
    int e = blockIdx.x * blockDim.x + threadIdx.x;
    if (e >= NE) return;
    int dst = ei[NE + e];
    int r = et[e];
    atomicAdd(&cnt[(size_t)r * NN + dst], 1.f);
}

__global__ void inv_kernel(const float* __restrict__ cnt, float* __restrict__ inv) {
    int i = blockIdx.x * blockDim.x + threadIdx.x;
    if (i < 2 * NN) inv[i] = 1.f / fmaxf(cnt[i], 1.f);
}

__global__ void zero_kernel(float4* __restrict__ p, long n4) {
    long i = blockIdx.x * (long)blockDim.x + threadIdx.x;
    long st = (long)gridDim.x * blockDim.x;
    for (; i < n4; i += st) p[i] = make_float4(0.f, 0.f, 0.f, 0.f);
}

// ---------------------------------------------------------------------------
// Final 128->2 projection: one warp per row
// ---------------------------------------------------------------------------
__global__ void out_kernel(const float* __restrict__ X, const float* __restrict__ W2,
                           const float* __restrict__ b2, float* __restrict__ out) {
    int gw = (blockIdx.x * blockDim.x + threadIdx.x) >> 5;
    int lane = threadIdx.x & 31;
    if (gw >= NN) return;
    float4 xv = *(const float4*)(X + (size_t)gw * 128 + lane * 4);
    float4 w0 = *(const float4*)(W2 + lane * 4);
    float4 w1 = *(const float4*)(W2 + 128 + lane * 4);
    float s0 = xv.x * w0.x + xv.y * w0.y + xv.z * w0.z + xv.w * w0.w;
    float s1 = xv.x * w1.x + xv.y * w1.y + xv.z * w1.z + xv.w * w1.w;
#pragma unroll
    for (int off = 16; off; off >>= 1) {
        s0 += __shfl_xor_sync(0xffffffffu, s0, off);
        s1 += __shfl_xor_sync(0xffffffffu, s1, off);
    }
    if (lane == 0) {
        out[(size_t)gw * 2 + 0] = s0 + b2[0];
        out[(size_t)gw * 2 + 1] = s1 + b2[1];
    }
}

// ---------------------------------------------------------------------------
extern "C" void kernel_launch(void* const* d_in, const int* in_sizes, int n_in,
                              void* d_out, int out_size) {
    const float* des   = (const float*)d_in[0];
    const float* tweet = (const float*)d_in[1];
    const float* nump  = (const float*)d_in[2];
    const float* catp  = (const float*)d_in[3];
    const int*   ei    = (const int*)d_in[4];
    const int*   et    = (const int*)d_in[5];
    const float* Wd  = (const float*)d_in[6];  const float* bd  = (const float*)d_in[7];
    const float* Wn  = (const float*)d_in[8];  const float* bn  = (const float*)d_in[9];
    const float* Wc  = (const float*)d_in[10]; const float* bc  = (const float*)d_in[11];
    const float* Wt  = (const float*)d_in[12]; const float* bt  = (const float*)d_in[13];
    const float* Win = (const float*)d_in[14]; const float* bin = (const float*)d_in[15];
    const float* rw    = (const float*)d_in[16];
    const float* rroot = (const float*)d_in[17];
    const float* rbias = (const float*)d_in[18];
    const float* Wo1 = (const float*)d_in[19]; const float* bo1 = (const float*)d_in[20];
    const float* Wo2 = (const float*)d_in[21]; const float* bo2 = (const float*)d_in[22];
    float* out = (float*)d_out;

    float *pA, *pB, *pAgg, *pCnt, *pInv;
    cudaGetSymbolAddress((void**)&pA, g_bufA);
    cudaGetSymbolAddress((void**)&pB, g_bufB);
    cudaGetSymbolAddress((void**)&pAgg, g_agg);
    cudaGetSymbolAddress((void**)&pCnt, g_cnt);
    cudaGetSymbolAddress((void**)&pInv, g_inv);

    const int GEMM_GRID = (NN + 127) / 128;

    // features -> A
    feat_kernel<<<NN / 2, dim3(128, 2)>>>(des, tweet, nump, catp, Wd, bd, Wn, bn, Wc, bc, Wt, bt, pA);
    // x = lrelu(feat @ W_in^T + b_in) -> B
    gemm_lin_kernel<1, 1><<<GEMM_GRID, 256>>>(pA, Win, bin, pB, NN);

    // degree counts (shared by both convs)
    zero_kernel<<<512, 256>>>((float4*)pCnt, (long)(2 * NN) / 4);
    count_kernel<<<(NE + 255) / 256, 256>>>(ei, et, pCnt);
    inv_kernel<<<(2 * NN + 255) / 256, 256>>>(pCnt, pInv);

    // conv1: B -> A
    zero_kernel<<<8192, 256>>>((float4*)pAgg, (long)2 * NN * 128 / 4);
    scatter_kernel<<<NE / 8, 256>>>(pB, ei, et, pAgg);
    gemm_conv_kernel<<<GEMM_GRID, 256>>>(pB, pAgg, pInv, rroot, rw, rbias, pA, NN);

    // conv2: A -> B
    zero_kernel<<<8192, 256>>>((float4*)pAgg, (long)2 * NN * 128 / 4);
    scatter_kernel<<<NE / 8, 256>>>(pA, ei, et, pAgg);
    gemm_conv_kernel<<<GEMM_GRID, 256>>>(pA, pAgg, pInv, rroot, rw, rbias, pB, NN);

    // x = lrelu(x @ W_o1^T + b_o1) -> A
    gemm_lin_kernel<1, 1><<<GEMM_GRID, 256>>>(pB, Wo1, bo1, pA, NN);
    // out = x @ W_o2^T + b_o2
    out_kernel<<<NN / 8, 256>>>(pA, Wo2, bo2, out);
}

// round 4
// speedup vs baseline: 3.3785x; 3.3785x over previous
#include <cuda_runtime.h>
#include <cuda_bf16.h>
#include <cstdint>

#define NU 100000
#define NT 100000
#define NN 200000
#define NE 600000

// ---- scratch (device globals; no runtime allocation) ----
__device__ float g_bufA[(size_t)NN * 128];
__device__ float g_bufB[(size_t)NN * 128];
__device__ float g_agg[(size_t)2 * NN * 128];
__device__ float g_cnt[2 * NN];
__device__ float g_inv[2 * NN];
// pre-converted weights, bf16 hi/lo, [N=128, Ktot] K-major rows:
// featU @0 (Ktot128), featT @16384, lin @32768, conv @49152 (Ktot384), o1 @98304
#define BTOT 114688
__device__ __align__(16) __nv_bfloat16 g_Bh[BTOT];
__device__ __align__(16) __nv_bfloat16 g_Bl[BTOT];
__device__ float g_biasU[128];

__device__ __forceinline__ float lrelu(float x) { return x > 0.f ? x : 0.01f * x; }

// ======================= PTX helpers (portable sm_80+) =======================
__device__ __forceinline__ uint32_t smem_to_u32(const void* p) {
    uint32_t a;
    asm("{ .reg .u64 t; cvta.to.shared.u64 t, %1; cvt.u32.u64 %0, t; }" : "=r"(a) : "l"(p));
    return a;
}
__device__ __forceinline__ void ldsm_x4(uint32_t& r0, uint32_t& r1, uint32_t& r2,
                                        uint32_t& r3, uint32_t a) {
    asm volatile("ldmatrix.sync.aligned.m8n8.x4.shared.b16 {%0,%1,%2,%3}, [%4];"
                 : "=r"(r0), "=r"(r1), "=r"(r2), "=r"(r3) : "r"(a));
}
__device__ __forceinline__ void ldsm_x2(uint32_t& r0, uint32_t& r1, uint32_t a) {
    asm volatile("ldmatrix.sync.aligned.m8n8.x2.shared.b16 {%0,%1}, [%2];"
                 : "=r"(r0), "=r"(r1) : "r"(a));
}
__device__ __forceinline__ void mma16816(float* d, uint32_t a0, uint32_t a1, uint32_t a2,
                                         uint32_t a3, uint32_t b0, uint32_t b1) {
    asm volatile(
        "mma.sync.aligned.m16n8k16.row.col.f32.bf16.bf16.f32 "
        "{%0,%1,%2,%3}, {%4,%5,%6,%7}, {%8,%9}, {%0,%1,%2,%3};"
        : "+f"(d[0]), "+f"(d[1]), "+f"(d[2]), "+f"(d[3])
        : "r"(a0), "r"(a1), "r"(a2), "r"(a3), "r"(b0), "r"(b1));
}
#define CP_ASYNC16(dst, src) \
    asm volatile("cp.async.ca.shared.global [%0], [%1], 16;" :: "r"(dst), "l"(src))
#define CP_COMMIT() asm volatile("cp.async.commit_group;" ::: "memory")
#define CP_WAIT0() asm volatile("cp.async.wait_group 0;" ::: "memory")

__device__ __forceinline__ uint32_t pk2(float a, float b) {
    __nv_bfloat16 ha = __float2bfloat16(a), hb = __float2bfloat16(b);
    return (uint32_t)__bfloat16_as_ushort(ha) | ((uint32_t)__bfloat16_as_ushort(hb) << 16);
}

// ======================= bf16x2 warp-MMA GEMM =======================
// C[M,128] = act( sum_seg A_seg[M,128]*scale_seg @ B_seg^T + bias )
// Block 256 thr, tile 128x128, warp tile 64x32, BK=32, double-buffered smem.
// smem buffer layout (bf16 elements, padded stride 40):
//   Ah @0, Al @5120, Bh @10240, Bl @15360 ; buffer size 20480 el = 40960 B
#define ASTR 40
#define AH_OFF 0
#define AL_OFF 5120
#define BH_OFF 10240
#define BL_OFF 15360
#define BUF_ELE 20480
#define GEMM_SMEM (2 * BUF_ELE * 2)

template <int NSEG, int RELU>
__global__ void __launch_bounds__(256) mma_gemm(
    const float* __restrict__ X, const float* __restrict__ Agg,
    const float* __restrict__ Inv,
    const __nv_bfloat16* __restrict__ Bh, const __nv_bfloat16* __restrict__ Bl,
    const float* __restrict__ bias, float* __restrict__ C, int M) {
    extern __shared__ __nv_bfloat16 sm[];
    const int KTOT = NSEG * 128;
    const int CHUNKS = NSEG * 4;
    int tid = threadIdx.x, lane = tid & 31, wid = tid >> 5;
    int warpM = wid & 1, warpN = wid >> 1;
    int rowBlock = blockIdx.x * 128;
    uint32_t smb = smem_to_u32(sm);

    int arow = tid >> 1, ahalf = tid & 1;  // A/B staging: 2 threads per row
    int grow = rowBlock + arow;
    bool rok = grow < M;

    float acc[4][4][4];
#pragma unroll
    for (int i = 0; i < 4; i++)
#pragma unroll
        for (int j = 0; j < 4; j++)
#pragma unroll
            for (int k = 0; k < 4; k++) acc[i][j][k] = 0.f;

    float4 ar[4];

    // ---- prologue: stage chunk 0 into buf 0 ----
    {
        const float* p = X + (size_t)grow * 128 + ahalf * 16;
#pragma unroll
        for (int i = 0; i < 4; i++)
            ar[i] = rok ? *(const float4*)(p + i * 4) : make_float4(0.f, 0.f, 0.f, 0.f);
        const __nv_bfloat16* bh = Bh + (size_t)arow * KTOT + ahalf * 16;
        const __nv_bfloat16* bl = Bl + (size_t)arow * KTOT + ahalf * 16;
        uint32_t dH = smb + (uint32_t)(BH_OFF + arow * ASTR + ahalf * 16) * 2;
        uint32_t dL = smb + (uint32_t)(BL_OFF + arow * ASTR + ahalf * 16) * 2;
        CP_ASYNC16(dH, bh); CP_ASYNC16(dH + 16, bh + 8);
        CP_ASYNC16(dL, bl); CP_ASYNC16(dL + 16, bl + 8);
        CP_COMMIT();
        __nv_bfloat16* dh = sm + AH_OFF + arow * ASTR + ahalf * 16;
        __nv_bfloat16* dl = sm + AL_OFF + arow * ASTR + ahalf * 16;
#pragma unroll
        for (int i = 0; i < 4; i++) {
            float4 v = ar[i];
            __nv_bfloat16 hx = __float2bfloat16(v.x), hy = __float2bfloat16(v.y);
            __nv_bfloat16 hz = __float2bfloat16(v.z), hw = __float2bfloat16(v.w);
            uint2 hu = make_uint2(
                (uint32_t)__bfloat16_as_ushort(hx) | ((uint32_t)__bfloat16_as_ushort(hy) << 16),
                (uint32_t)__bfloat16_as_ushort(hz) | ((uint32_t)__bfloat16_as_ushort(hw) << 16));
            uint2 lu = make_uint2(pk2(v.x - __bfloat162float(hx), v.y - __bfloat162float(hy)),
                                  pk2(v.z - __bfloat162float(hz), v.w - __bfloat162float(hw)));
            *(uint2*)(dh + i * 4) = hu;
            *(uint2*)(dl + i * 4) = lu;
        }
    }
    CP_WAIT0();
    __syncthreads();

    int lr8 = lane & 7, lb = lane >> 3, l16 = lane & 15;

    for (int c = 0; c < CHUNKS; c++) {
        int buf = c & 1;
        uint32_t base = smb + (uint32_t)buf * BUF_ELE * 2;
        bool hasNext = (c + 1) < CHUNKS;

        if (hasNext) {
            int cn = c + 1;
            int seg = cn >> 2, kin = (cn & 3) * 32;
            // B -> cp.async into other buffer
            const __nv_bfloat16* bh = Bh + (size_t)arow * KTOT + cn * 32 + ahalf * 16;
            const __nv_bfloat16* bl = Bl + (size_t)arow * KTOT + cn * 32 + ahalf * 16;
            uint32_t off = (uint32_t)((buf ^ 1) * BUF_ELE + arow * ASTR + ahalf * 16) * 2;
            uint32_t dH = smb + off + BH_OFF * 2;
            uint32_t dL = smb + off + BL_OFF * 2;
            CP_ASYNC16(dH, bh); CP_ASYNC16(dH + 16, bh + 8);
            CP_ASYNC16(dL, bl); CP_ASYNC16(dL + 16, bl + 8);
            CP_COMMIT();
            // A -> regs (scaled)
            const float* Ap = (seg == 0) ? X : Agg + (size_t)(seg - 1) * NN * 128;
            float s = 1.f;
            if (NSEG > 1 && seg > 0 && rok) s = Inv[(size_t)(seg - 1) * NN + grow];
            const float* p = Ap + (size_t)grow * 128 + kin + ahalf * 16;
#pragma unroll
            for (int i = 0; i < 4; i++) {
                float4 v = rok ? *(const float4*)(p + i * 4) : make_float4(0.f, 0.f, 0.f, 0.f);
                v.x *= s; v.y *= s; v.z *= s; v.w *= s;
                ar[i] = v;
            }
        }

        // ---- MMA on current buffer ----
        {
            uint32_t aH = base + AH_OFF * 2, aL = base + AL_OFF * 2;
            uint32_t bH = base + BH_OFF * 2, bL = base + BL_OFF * 2;
#pragma unroll
            for (int ks = 0; ks < 2; ks++) {
                uint32_t bhf[4][2], blf[4][2];
                int bCol = ks * 16 + (l16 >> 3) * 8;
#pragma unroll
                for (int ni = 0; ni < 4; ni++) {
                    int bRow = warpN * 32 + ni * 8 + (l16 & 7);
                    uint32_t o = (uint32_t)(bRow * ASTR + bCol) * 2;
                    ldsm_x2(bhf[ni][0], bhf[ni][1], bH + o);
                    ldsm_x2(blf[ni][0], blf[ni][1], bL + o);
                }
                int aCol = ks * 16 + (lb >> 1) * 8;
#pragma unroll
                for (int mi = 0; mi < 4; mi++) {
                    int aRow = warpM * 64 + mi * 16 + (lb & 1) * 8 + lr8;
                    uint32_t o = (uint32_t)(aRow * ASTR + aCol) * 2;
                    uint32_t a0, a1, a2, a3, q0, q1, q2, q3;
                    ldsm_x4(a0, a1, a2, a3, aH + o);
                    ldsm_x4(q0, q1, q2, q3, aL + o);
#pragma unroll
                    for (int ni = 0; ni < 4; ni++) {
                        mma16816(acc[mi][ni], a0, a1, a2, a3, bhf[ni][0], bhf[ni][1]);
                        mma16816(acc[mi][ni], a0, a1, a2, a3, blf[ni][0], blf[ni][1]);
                        mma16816(acc[mi][ni], q0, q1, q2, q3, bhf[ni][0], bhf[ni][1]);
                    }
                }
            }
        }

        if (hasNext) {
            __nv_bfloat16* dh = sm + (buf ^ 1) * BUF_ELE + AH_OFF + arow * ASTR + ahalf * 16;
            __nv_bfloat16* dl = sm + (buf ^ 1) * BUF_ELE + AL_OFF + arow * ASTR + ahalf * 16;
#pragma unroll
            for (int i = 0; i < 4; i++) {
                float4 v = ar[i];
                __nv_bfloat16 hx = __float2bfloat16(v.x), hy = __float2bfloat16(v.y);
                __nv_bfloat16 hz = __float2bfloat16(v.z), hw = __float2bfloat16(v.w);
                uint2 hu = make_uint2(
                    (uint32_t)__bfloat16_as_ushort(hx) | ((uint32_t)__bfloat16_as_ushort(hy) << 16),
                    (uint32_t)__bfloat16_as_ushort(hz) | ((uint32_t)__bfloat16_as_ushort(hw) << 16));
                uint2 lu = make_uint2(pk2(v.x - __bfloat162float(hx), v.y - __bfloat162float(hy)),
                                      pk2(v.z - __bfloat162float(hz), v.w - __bfloat162float(hw)));
                *(uint2*)(dh + i * 4) = hu;
                *(uint2*)(dl + i * 4) = lu;
            }
        }
        CP_WAIT0();
        __syncthreads();
    }

    // ---- epilogue: bias + act, direct stores ----
    int gid = lane >> 2, qid = lane & 3;
#pragma unroll
    for (int mi = 0; mi < 4; mi++) {
        int r0 = rowBlock + warpM * 64 + mi * 16 + gid;
        int r1 = r0 + 8;
#pragma unroll
        for (int ni = 0; ni < 4; ni++) {
            int cb = warpN * 32 + ni * 8 + qid * 2;
            float b0 = bias[cb], b1 = bias[cb + 1];
            float v0 = acc[mi][ni][0] + b0, v1 = acc[mi][ni][1] + b1;
            float v2 = acc[mi][ni][2] + b0, v3 = acc[mi][ni][3] + b1;
            if (RELU) { v0 = lrelu(v0); v1 = lrelu(v1); v2 = lrelu(v2); v3 = lrelu(v3); }
            if (r0 < M) { float2 t = make_float2(v0, v1); *(float2*)(C + (size_t)r0 * 128 + cb) = t; }
            if (r1 < M) { float2 t = make_float2(v2, v3); *(float2*)(C + (size_t)r1 * 128 + cb) = t; }
        }
    }
}

// ======================= feature packing =======================
__global__ void pack_kernel(const float* __restrict__ des, const float* __restrict__ tweet,
                            const float* __restrict__ nump, const float* __restrict__ catp,
                            float* __restrict__ P) {
    long idx = blockIdx.x * 256L + threadIdx.x;
    if (idx >= (long)NN * 128) return;
    int row = (int)(idx >> 7), col = (int)(idx & 127);
    float v = 0.f;
    if (row < NU) {
        if (col < 100) v = des[(size_t)row * 100 + col];
        else if (col < 106) v = nump[(size_t)row * 6 + (col - 100)];
        else if (col < 117) v = catp[(size_t)row * 11 + (col - 106)];
    } else {
        if (col < 100) v = tweet[(size_t)(row - NU) * 100 + col];
    }
    P[idx] = v;
}

// ======================= weight pre-conversion =======================
__global__ void prep_B_kernel(const float* __restrict__ Wd, const float* __restrict__ bd,
                              const float* __restrict__ Wn, const float* __restrict__ bn,
                              const float* __restrict__ Wc, const float* __restrict__ bc,
                              const float* __restrict__ Wt, const float* __restrict__ Win,
                              const float* __restrict__ root, const float* __restrict__ rw,
                              const float* __restrict__ Wo1) {
    int idx = blockIdx.x * 256 + threadIdx.x;
    if (idx >= BTOT + 128) return;
    if (idx >= BTOT) {
        int n = idx - BTOT;
        g_biasU[n] = (n < 64) ? bd[n] : (n < 96) ? bn[n - 64] : bc[n - 96];
        return;
    }
    float v = 0.f;
    if (idx < 16384) {  // featU blockdiag [n,k=128]
        int n = idx >> 7, k = idx & 127;
        if (n < 64) { if (k < 100) v = Wd[n * 100 + k]; }
        else if (n < 96) { if (k >= 100 && k < 106) v = Wn[(n - 64) * 6 + (k - 100)]; }
        else { if (k >= 106 && k < 117) v = Wc[(n - 96) * 11 + (k - 106)]; }
    } else if (idx < 32768) {  // featT
        int l = idx - 16384;
        int n = l >> 7, k = l & 127;
        if (k < 100) v = Wt[n * 100 + k];
    } else if (idx < 49152) {  // lin (W_in already [N,K])
        v = Win[idx - 32768];
    } else if (idx < 98304) {  // conv: [n, k=384]: seg0 root^T, seg1/2 rw^T
        int l = idx - 49152;
        int n = l / 384, k = l % 384;
        if (k < 128) v = root[k * 128 + n];
        else if (k < 256) v = rw[(k - 128) * 128 + n];
        else v = rw[16384 + (k - 256) * 128 + n];
    } else {  // o1
        v = Wo1[idx - 98304];
    }
    __nv_bfloat16 h = __float2bfloat16(v);
    g_Bh[idx] = h;
    g_Bl[idx] = __float2bfloat16(v - __bfloat162float(h));
}

// ======================= graph ops =======================
__global__ void scatter_kernel(const float* __restrict__ X, const int* __restrict__ ei,
                               const int* __restrict__ et, float* __restrict__ Agg) {
    int w = (blockIdx.x * blockDim.x + threadIdx.x) >> 5;
    int lane = threadIdx.x & 31;
    if (w >= NE) return;
    int src = ei[w];
    int dst = ei[NE + w];
    int r = et[w];
    float4 v = *(const float4*)(X + (size_t)src * 128 + lane * 4);
    atomicAdd((float4*)(Agg + ((size_t)r * NN + dst) * 128 + lane * 4), v);
}

__global__ void count_kernel(const int* __restrict__ ei, const int* __restrict__ et,
                             float* __restrict__ cnt) {
    int e = blockIdx.x * blockDim.x + threadIdx.x;
    if (e >= NE) return;
    atomicAdd(&cnt[(size_t)et[e] * NN + ei[NE + e]], 1.f);
}

__global__ void inv_kernel(const float* __restrict__ cnt, float* __restrict__ inv) {
    int i = blockIdx.x * blockDim.x + threadIdx.x;
    if (i < 2 * NN) inv[i] = 1.f / fmaxf(cnt[i], 1.f);
}

__global__ void zero_kernel(float4* __restrict__ p, long n4) {
    long i = blockIdx.x * (long)blockDim.x + threadIdx.x;
    long st = (long)gridDim.x * blockDim.x;
    for (; i < n4; i += st) p[i] = make_float4(0.f, 0.f, 0.f, 0.f);
}

__global__ void out_kernel(const float* __restrict__ X, const float* __restrict__ W2,
                           const float* __restrict__ b2, float* __restrict__ out) {
    int gw = (blockIdx.x * blockDim.x + threadIdx.x) >> 5;
    int lane = threadIdx.x & 31;
    if (gw >= NN) return;
    float4 xv = *(const float4*)(X + (size_t)gw * 128 + lane * 4);
    float4 w0 = *(const float4*)(W2 + lane * 4);
    float4 w1 = *(const float4*)(W2 + 128 + lane * 4);
    float s0 = xv.x * w0.x + xv.y * w0.y + xv.z * w0.z + xv.w * w0.w;
    float s1 = xv.x * w1.x + xv.y * w1.y + xv.z * w1.z + xv.w * w1.w;
#pragma unroll
    for (int off = 16; off; off >>= 1) {
        s0 += __shfl_xor_sync(0xffffffffu, s0, off);
        s1 += __shfl_xor_sync(0xffffffffu, s1, off);
    }
    if (lane == 0) {
        out[(size_t)gw * 2 + 0] = s0 + b2[0];
        out[(size_t)gw * 2 + 1] = s1 + b2[1];
    }
}

// ---------------------------------------------------------------------------
extern "C" void kernel_launch(void* const* d_in, const int* in_sizes, int n_in,
                              void* d_out, int out_size) {
    const float* des   = (const float*)d_in[0];
    const float* tweet = (const float*)d_in[1];
    const float* nump  = (const float*)d_in[2];
    const float* catp  = (const float*)d_in[3];
    const int*   ei    = (const int*)d_in[4];
    const int*   et    = (const int*)d_in[5];
    const float* Wd  = (const float*)d_in[6];  const float* bd  = (const float*)d_in[7];
    const float* Wn  = (const float*)d_in[8];  const float* bn  = (const float*)d_in[9];
    const float* Wc  = (const float*)d_in[10]; const float* bc  = (const float*)d_in[11];
    const float* Wt  = (const float*)d_in[12]; const float* bt  = (const float*)d_in[13];
    const float* Win = (const float*)d_in[14]; const float* bin = (const float*)d_in[15];
    const float* rw    = (const float*)d_in[16];
    const float* rroot = (const float*)d_in[17];
    const float* rbias = (const float*)d_in[18];
    const float* Wo1 = (const float*)d_in[19]; const float* bo1 = (const float*)d_in[20];
    const float* Wo2 = (const float*)d_in[21]; const float* bo2 = (const float*)d_in[22];
    float* out = (float*)d_out;

    float *pA, *pB, *pAgg, *pCnt, *pInv, *pBiasU;
    __nv_bfloat16 *pBh, *pBl;
    cudaGetSymbolAddress((void**)&pA, g_bufA);
    cudaGetSymbolAddress((void**)&pB, g_bufB);
    cudaGetSymbolAddress((void**)&pAgg, g_agg);
    cudaGetSymbolAddress((void**)&pCnt, g_cnt);
    cudaGetSymbolAddress((void**)&pInv, g_inv);
    cudaGetSymbolAddress((void**)&pBh, g_Bh);
    cudaGetSymbolAddress((void**)&pBl, g_Bl);
    cudaGetSymbolAddress((void**)&pBiasU, g_biasU);

    cudaFuncSetAttribute(mma_gemm<1, 1>, cudaFuncAttributeMaxDynamicSharedMemorySize, GEMM_SMEM);
    cudaFuncSetAttribute(mma_gemm<1, 0>, cudaFuncAttributeMaxDynamicSharedMemorySize, GEMM_SMEM);
    cudaFuncSetAttribute(mma_gemm<3, 0>, cudaFuncAttributeMaxDynamicSharedMemorySize, GEMM_SMEM);

    const int GU = (NU + 127) / 128;   // 782
    const int GN = (NN + 127) / 128;   // 1563

    // pack inputs -> B ; pre-convert weights
    pack_kernel<<<(NN * 128 + 255) / 256, 256>>>(des, tweet, nump, catp, pB);
    prep_B_kernel<<<(BTOT + 128 + 255) / 256, 256>>>(Wd, bd, Wn, bn, Wc, bc, Wt, Win,
                                                     rroot, rw, Wo1);
    // degree counts (independent)
    zero_kernel<<<512, 256>>>((float4*)pCnt, (long)(2 * NN) / 4);
    count_kernel<<<(NE + 255) / 256, 256>>>(ei, et, pCnt);
    inv_kernel<<<(2 * NN + 255) / 256, 256>>>(pCnt, pInv);

    // feature MLPs as GEMMs -> A
    mma_gemm<1, 1><<<GU, 256, GEMM_SMEM>>>(pB, nullptr, nullptr, pBh, pBl, pBiasU, pA, NU);
    mma_gemm<1, 1><<<GU, 256, GEMM_SMEM>>>(pB + (size_t)NU * 128, nullptr, nullptr,
                                           pBh + 16384, pBl + 16384, bt,
                                           pA + (size_t)NU * 128, NU);
    // x = lrelu(x @ W_in^T + b_in): A -> B
    mma_gemm<1, 1><<<GN, 256, GEMM_SMEM>>>(pA, nullptr, nullptr, pBh + 32768, pBl + 32768,
                                           bin, pB, NN);
    // conv1: B -> A
    zero_kernel<<<8192, 256>>>((float4*)pAgg, (long)2 * NN * 128 / 4);
    scatter_kernel<<<NE / 8, 256>>>(pB, ei, et, pAgg);
    mma_gemm<3, 0><<<GN, 256, GEMM_SMEM>>>(pB, pAgg, pInv, pBh + 49152, pBl + 49152,
                                           rbias, pA, NN);
    // conv2: A -> B
    zero_kernel<<<8192, 256>>>((float4*)pAgg, (long)2 * NN * 128 / 4);
    scatter_kernel<<<NE / 8, 256>>>(pA, ei, et, pAgg);
    mma_gemm<3, 0><<<GN, 256, GEMM_SMEM>>>(pA, pAgg, pInv, pBh + 49152, pBl + 49152,
                                           rbias, pB, NN);
    // x = lrelu(x @ W_o1^T + b_o1): B -> A
    mma_gemm<1, 1><<<GN, 256, GEMM_SMEM>>>(pB, nullptr, nullptr, pBh + 98304, pBl + 98304,
                                           bo1, pA, NN);
    // out = x @ W_o2^T + b_o2
    out_kernel<<<NN / 8, 256>>>(pA, Wo2, bo2, out);
}

// round 5
// speedup vs baseline: 4.0685x; 1.2042x over previous
#include <cuda_runtime.h>
#include <cuda_bf16.h>
#include <cstdint>

#define NU 100000
#define NT 100000
#define NN 200000
#define NE 600000
#define NSLOT (2 * NN)

// ---- scratch (device globals; no runtime allocation) ----
__device__ float g_bufA[(size_t)NN * 128];
__device__ float g_bufB[(size_t)NN * 128];
__device__ float g_agg[(size_t)2 * NN * 128];
// CSR structures
__device__ int g_cnt[NSLOT];
__device__ int g_off[NSLOT];
__device__ int g_cur[NSLOT];
__device__ int g_bsum[1024];
__device__ int g_esrc[NE];
// pre-converted weights, bf16 hi/lo, [N=128, Ktot] K-major rows:
// featU @0 (Ktot128), featT @16384, lin @32768, conv @49152 (Ktot384), o1 @98304
#define BTOT 114688
__device__ __align__(16) __nv_bfloat16 g_Bh[BTOT];
__device__ __align__(16) __nv_bfloat16 g_Bl[BTOT];
__device__ float g_biasU[128];

__device__ __forceinline__ float lrelu(float x) { return x > 0.f ? x : 0.01f * x; }

// ======================= PTX helpers (portable sm_80+) =======================
__device__ __forceinline__ uint32_t smem_to_u32(const void* p) {
    uint32_t a;
    asm("{ .reg .u64 t; cvta.to.shared.u64 t, %1; cvt.u32.u64 %0, t; }" : "=r"(a) : "l"(p));
    return a;
}
__device__ __forceinline__ void ldsm_x4(uint32_t& r0, uint32_t& r1, uint32_t& r2,
                                        uint32_t& r3, uint32_t a) {
    asm volatile("ldmatrix.sync.aligned.m8n8.x4.shared.b16 {%0,%1,%2,%3}, [%4];"
                 : "=r"(r0), "=r"(r1), "=r"(r2), "=r"(r3) : "r"(a));
}
__device__ __forceinline__ void ldsm_x2(uint32_t& r0, uint32_t& r1, uint32_t a) {
    asm volatile("ldmatrix.sync.aligned.m8n8.x2.shared.b16 {%0,%1}, [%2];"
                 : "=r"(r0), "=r"(r1) : "r"(a));
}
__device__ __forceinline__ void mma16816(float* d, uint32_t a0, uint32_t a1, uint32_t a2,
                                         uint32_t a3, uint32_t b0, uint32_t b1) {
    asm volatile(
        "mma.sync.aligned.m16n8k16.row.col.f32.bf16.bf16.f32 "
        "{%0,%1,%2,%3}, {%4,%5,%6,%7}, {%8,%9}, {%0,%1,%2,%3};"
        : "+f"(d[0]), "+f"(d[1]), "+f"(d[2]), "+f"(d[3])
        : "r"(a0), "r"(a1), "r"(a2), "r"(a3), "r"(b0), "r"(b1));
}
#define CP_ASYNC16(dst, src) \
    asm volatile("cp.async.ca.shared.global [%0], [%1], 16;" :: "r"(dst), "l"(src))
#define CP_COMMIT() asm volatile("cp.async.commit_group;" ::: "memory")
#define CP_WAIT0() asm volatile("cp.async.wait_group 0;" ::: "memory")

__device__ __forceinline__ uint32_t pk2(float a, float b) {
    __nv_bfloat16 ha = __float2bfloat16(a), hb = __float2bfloat16(b);
    return (uint32_t)__bfloat16_as_ushort(ha) | ((uint32_t)__bfloat16_as_ushort(hb) << 16);
}

// ======================= bf16x2 warp-MMA GEMM =======================
// C[M,128] = act( sum_seg A_seg[M,128] @ B_seg^T + bias )
// Block 256 thr, tile 128x128, warp tile 64x32, BK=32, double-buffered smem.
#define ASTR 40
#define AH_OFF 0
#define AL_OFF 5120
#define BH_OFF 10240
#define BL_OFF 15360
#define BUF_ELE 20480
#define GEMM_SMEM (2 * BUF_ELE * 2)

template <int NSEG, int RELU>
__global__ void __launch_bounds__(256) mma_gemm(
    const float* __restrict__ X, const float* __restrict__ Agg,
    const __nv_bfloat16* __restrict__ Bh, const __nv_bfloat16* __restrict__ Bl,
    const float* __restrict__ bias, float* __restrict__ C, int M) {
    extern __shared__ __nv_bfloat16 sm[];
    const int KTOT = NSEG * 128;
    const int CHUNKS = NSEG * 4;
    int tid = threadIdx.x, lane = tid & 31, wid = tid >> 5;
    int warpM = wid & 1, warpN = wid >> 1;
    int rowBlock = blockIdx.x * 128;
    uint32_t smb = smem_to_u32(sm);

    int arow = tid >> 1, ahalf = tid & 1;
    int grow = rowBlock + arow;
    bool rok = grow < M;

    float acc[4][4][4];
#pragma unroll
    for (int i = 0; i < 4; i++)
#pragma unroll
        for (int j = 0; j < 4; j++)
#pragma unroll
            for (int k = 0; k < 4; k++) acc[i][j][k] = 0.f;

    float4 ar[4];

    // ---- prologue: stage chunk 0 into buf 0 ----
    {
        const float* p = X + (size_t)grow * 128 + ahalf * 16;
#pragma unroll
        for (int i = 0; i < 4; i++)
            ar[i] = rok ? *(const float4*)(p + i * 4) : make_float4(0.f, 0.f, 0.f, 0.f);
        const __nv_bfloat16* bh = Bh + (size_t)arow * KTOT + ahalf * 16;
        const __nv_bfloat16* bl = Bl + (size_t)arow * KTOT + ahalf * 16;
        uint32_t dH = smb + (uint32_t)(BH_OFF + arow * ASTR + ahalf * 16) * 2;
        uint32_t dL = smb + (uint32_t)(BL_OFF + arow * ASTR + ahalf * 16) * 2;
        CP_ASYNC16(dH, bh); CP_ASYNC16(dH + 16, bh + 8);
        CP_ASYNC16(dL, bl); CP_ASYNC16(dL + 16, bl + 8);
        CP_COMMIT();
        __nv_bfloat16* dh = sm + AH_OFF + arow * ASTR + ahalf * 16;
        __nv_bfloat16* dl = sm + AL_OFF + arow * ASTR + ahalf * 16;
#pragma unroll
        for (int i = 0; i < 4; i++) {
            float4 v = ar[i];
            __nv_bfloat16 hx = __float2bfloat16(v.x), hy = __float2bfloat16(v.y);
            __nv_bfloat16 hz = __float2bfloat16(v.z), hw = __float2bfloat16(v.w);
            uint2 hu = make_uint2(
                (uint32_t)__bfloat16_as_ushort(hx) | ((uint32_t)__bfloat16_as_ushort(hy) << 16),
                (uint32_t)__bfloat16_as_ushort(hz) | ((uint32_t)__bfloat16_as_ushort(hw) << 16));
            uint2 lu = make_uint2(pk2(v.x - __bfloat162float(hx), v.y - __bfloat162float(hy)),
                                  pk2(v.z - __bfloat162float(hz), v.w - __bfloat162float(hw)));
            *(uint2*)(dh + i * 4) = hu;
            *(uint2*)(dl + i * 4) = lu;
        }
    }
    CP_WAIT0();
    __syncthreads();

    int lr8 = lane & 7, lb = lane >> 3, l16 = lane & 15;

    for (int c = 0; c < CHUNKS; c++) {
        int buf = c & 1;
        uint32_t base = smb + (uint32_t)buf * BUF_ELE * 2;
        bool hasNext = (c + 1) < CHUNKS;

        if (hasNext) {
            int cn = c + 1;
            int seg = cn >> 2, kin = (cn & 3) * 32;
            const __nv_bfloat16* bh = Bh + (size_t)arow * KTOT + cn * 32 + ahalf * 16;
            const __nv_bfloat16* bl = Bl + (size_t)arow * KTOT + cn * 32 + ahalf * 16;
            uint32_t off = (uint32_t)((buf ^ 1) * BUF_ELE + arow * ASTR + ahalf * 16) * 2;
            uint32_t dH = smb + off + BH_OFF * 2;
            uint32_t dL = smb + off + BL_OFF * 2;
            CP_ASYNC16(dH, bh); CP_ASYNC16(dH + 16, bh + 8);
            CP_ASYNC16(dL, bl); CP_ASYNC16(dL + 16, bl + 8);
            CP_COMMIT();
            const float* Ap = (seg == 0) ? X : Agg + (size_t)(seg - 1) * NN * 128;
            const float* p = Ap + (size_t)grow * 128 + kin + ahalf * 16;
#pragma unroll
            for (int i = 0; i < 4; i++)
                ar[i] = rok ? *(const float4*)(p + i * 4) : make_float4(0.f, 0.f, 0.f, 0.f);
        }

        // ---- MMA on current buffer ----
        {
            uint32_t aH = base + AH_OFF * 2, aL = base + AL_OFF * 2;
            uint32_t bH = base + BH_OFF * 2, bL = base + BL_OFF * 2;
#pragma unroll
            for (int ks = 0; ks < 2; ks++) {
                uint32_t bhf[4][2], blf[4][2];
                int bCol = ks * 16 + (l16 >> 3) * 8;
#pragma unroll
                for (int ni = 0; ni < 4; ni++) {
                    int bRow = warpN * 32 + ni * 8 + (l16 & 7);
                    uint32_t o = (uint32_t)(bRow * ASTR + bCol) * 2;
                    ldsm_x2(bhf[ni][0], bhf[ni][1], bH + o);
                    ldsm_x2(blf[ni][0], blf[ni][1], bL + o);
                }
                int aCol = ks * 16 + (lb >> 1) * 8;
#pragma unroll
                for (int mi = 0; mi < 4; mi++) {
                    int aRow = warpM * 64 + mi * 16 + (lb & 1) * 8 + lr8;
                    uint32_t o = (uint32_t)(aRow * ASTR + aCol) * 2;
                    uint32_t a0, a1, a2, a3, q0, q1, q2, q3;
                    ldsm_x4(a0, a1, a2, a3, aH + o);
                    ldsm_x4(q0, q1, q2, q3, aL + o);
#pragma unroll
                    for (int ni = 0; ni < 4; ni++) {
                        mma16816(acc[mi][ni], a0, a1, a2, a3, bhf[ni][0], bhf[ni][1]);
                        mma16816(acc[mi][ni], a0, a1, a2, a3, blf[ni][0], blf[ni][1]);
                        mma16816(acc[mi][ni], q0, q1, q2, q3, bhf[ni][0], bhf[ni][1]);
                    }
                }
            }
        }

        if (hasNext) {
            __nv_bfloat16* dh = sm + (buf ^ 1) * BUF_ELE + AH_OFF + arow * ASTR + ahalf * 16;
            __nv_bfloat16* dl = sm + (buf ^ 1) * BUF_ELE + AL_OFF + arow * ASTR + ahalf * 16;
#pragma unroll
            for (int i = 0; i < 4; i++) {
                float4 v = ar[i];
                __nv_bfloat16 hx = __float2bfloat16(v.x), hy = __float2bfloat16(v.y);
                __nv_bfloat16 hz = __float2bfloat16(v.z), hw = __float2bfloat16(v.w);
                uint2 hu = make_uint2(
                    (uint32_t)__bfloat16_as_ushort(hx) | ((uint32_t)__bfloat16_as_ushort(hy) << 16),
                    (uint32_t)__bfloat16_as_ushort(hz) | ((uint32_t)__bfloat16_as_ushort(hw) << 16));
                uint2 lu = make_uint2(pk2(v.x - __bfloat162float(hx), v.y - __bfloat162float(hy)),
                                      pk2(v.z - __bfloat162float(hz), v.w - __bfloat162float(hw)));
                *(uint2*)(dh + i * 4) = hu;
                *(uint2*)(dl + i * 4) = lu;
            }
        }
        CP_WAIT0();
        __syncthreads();
    }

    // ---- epilogue ----
    int gid = lane >> 2, qid = lane & 3;
#pragma unroll
    for (int mi = 0; mi < 4; mi++) {
        int r0 = rowBlock + warpM * 64 + mi * 16 + gid;
        int r1 = r0 + 8;
#pragma unroll
        for (int ni = 0; ni < 4; ni++) {
            int cb = warpN * 32 + ni * 8 + qid * 2;
            float b0 = bias[cb], b1 = bias[cb + 1];
            float v0 = acc[mi][ni][0] + b0, v1 = acc[mi][ni][1] + b1;
            float v2 = acc[mi][ni][2] + b0, v3 = acc[mi][ni][3] + b1;
            if (RELU) { v0 = lrelu(v0); v1 = lrelu(v1); v2 = lrelu(v2); v3 = lrelu(v3); }
            if (r0 < M) { float2 t = make_float2(v0, v1); *(float2*)(C + (size_t)r0 * 128 + cb) = t; }
            if (r1 < M) { float2 t = make_float2(v2, v3); *(float2*)(C + (size_t)r1 * 128 + cb) = t; }
        }
    }
}

// ======================= feature packing =======================
__global__ void pack_kernel(const float* __restrict__ des, const float* __restrict__ tweet,
                            const float* __restrict__ nump, const float* __restrict__ catp,
                            float* __restrict__ P) {
    long idx = blockIdx.x * 256L + threadIdx.x;
    if (idx >= (long)NN * 128) return;
    int row = (int)(idx >> 7), col = (int)(idx & 127);
    float v = 0.f;
    if (row < NU) {
        if (col < 100) v = des[(size_t)row * 100 + col];
        else if (col < 106) v = nump[(size_t)row * 6 + (col - 100)];
        else if (col < 117) v = catp[(size_t)row * 11 + (col - 106)];
    } else {
        if (col < 100) v = tweet[(size_t)(row - NU) * 100 + col];
    }
    P[idx] = v;
}

// ======================= weight pre-conversion =======================
__global__ void prep_B_kernel(const float* __restrict__ Wd, const float* __restrict__ bd,
                              const float* __restrict__ Wn, const float* __restrict__ bn,
                              const float* __restrict__ Wc, const float* __restrict__ bc,
                              const float* __restrict__ Wt, const float* __restrict__ Win,
                              const float* __restrict__ root, const float* __restrict__ rw,
                              const float* __restrict__ Wo1) {
    int idx = blockIdx.x * 256 + threadIdx.x;
    if (idx >= BTOT + 128) return;
    if (idx >= BTOT) {
        int n = idx - BTOT;
        g_biasU[n] = (n < 64) ? bd[n] : (n < 96) ? bn[n - 64] : bc[n - 96];
        return;
    }
    float v = 0.f;
    if (idx < 16384) {  // featU blockdiag [n,k=128]
        int n = idx >> 7, k = idx & 127;
        if (n < 64) { if (k < 100) v = Wd[n * 100 + k]; }
        else if (n < 96) { if (k >= 100 && k < 106) v = Wn[(n - 64) * 6 + (k - 100)]; }
        else { if (k >= 106 && k < 117) v = Wc[(n - 96) * 11 + (k - 106)]; }
    } else if (idx < 32768) {  // featT
        int l = idx - 16384;
        int n = l >> 7, k = l & 127;
        if (k < 100) v = Wt[n * 100 + k];
    } else if (idx < 49152) {  // lin
        v = Win[idx - 32768];
    } else if (idx < 98304) {  // conv: [n, k=384]: seg0 root^T, seg1/2 rw^T
        int l = idx - 49152;
        int n = l / 384, k = l % 384;
        if (k < 128) v = root[k * 128 + n];
        else if (k < 256) v = rw[(k - 128) * 128 + n];
        else v = rw[16384 + (k - 256) * 128 + n];
    } else {  // o1
        v = Wo1[idx - 98304];
    }
    __nv_bfloat16 h = __float2bfloat16(v);
    g_Bh[idx] = h;
    g_Bl[idx] = __float2bfloat16(v - __bfloat162float(h));
}

// ======================= CSR build =======================
__global__ void zero2_kernel(int* __restrict__ a, int* __restrict__ b, int n) {
    int i = blockIdx.x * 256 + threadIdx.x;
    if (i < n) { a[i] = 0; b[i] = 0; }
}

__global__ void count_kernel(const int* __restrict__ ei, const int* __restrict__ et,
                             int* __restrict__ cnt) {
    int e = blockIdx.x * 256 + threadIdx.x;
    if (e >= NE) return;
    atomicAdd(&cnt[et[e] * NN + ei[NE + e]], 1);
}

#define SCAN_BS 512
__global__ void scan1_kernel(const int* __restrict__ cnt, int* __restrict__ off,
                             int* __restrict__ bsum, int n) {
    __shared__ int sh[SCAN_BS];
    int t = threadIdx.x;
    int i = blockIdx.x * SCAN_BS + t;
    int v = (i < n) ? cnt[i] : 0;
    sh[t] = v;
    __syncthreads();
#pragma unroll
    for (int d = 1; d < SCAN_BS; d <<= 1) {
        int x = (t >= d) ? sh[t - d] : 0;
        __syncthreads();
        sh[t] += x;
        __syncthreads();
    }
    if (i < n) off[i] = sh[t] - v;  // exclusive within block
    if (t == SCAN_BS - 1) bsum[blockIdx.x] = sh[t];
}

__global__ void scan2_kernel(int* __restrict__ bsum, int nb) {
    __shared__ int sh[1024];
    int t = threadIdx.x;
    int v = (t < nb) ? bsum[t] : 0;
    sh[t] = v;
    __syncthreads();
#pragma unroll
    for (int d = 1; d < 1024; d <<= 1) {
        int x = (t >= d) ? sh[t - d] : 0;
        __syncthreads();
        sh[t] += x;
        __syncthreads();
    }
    if (t < nb) bsum[t] = sh[t] - v;  // exclusive
}

__global__ void scan3_kernel(int* __restrict__ off, const int* __restrict__ bsum, int n) {
    int i = blockIdx.x * SCAN_BS + threadIdx.x;
    if (i < n) off[i] += bsum[blockIdx.x];
}

__global__ void fill_kernel(const int* __restrict__ ei, const int* __restrict__ et,
                            const int* __restrict__ off, int* __restrict__ cur,
                            int* __restrict__ esrc) {
    int e = blockIdx.x * 256 + threadIdx.x;
    if (e >= NE) return;
    int slot = et[e] * NN + ei[NE + e];
    int pos = off[slot] + atomicAdd(&cur[slot], 1);
    esrc[pos] = ei[e];
}

// ======================= CSR gather-mean aggregation =======================
// one warp per (rel,dst) slot; writes mean directly (no atomics, no zeroing)
__global__ void agg_kernel(const float* __restrict__ X, const int* __restrict__ off,
                           const int* __restrict__ cnt, const int* __restrict__ esrc,
                           float* __restrict__ Agg) {
    int w = (blockIdx.x * blockDim.x + threadIdx.x) >> 5;
    int lane = threadIdx.x & 31;
    if (w >= NSLOT) return;
    int beg = off[w], deg = cnt[w];
    float4 acc = make_float4(0.f, 0.f, 0.f, 0.f);
    for (int i = 0; i < deg; i++) {
        int src = __ldg(&esrc[beg + i]);
        float4 v = *(const float4*)(X + (size_t)src * 128 + lane * 4);
        acc.x += v.x; acc.y += v.y; acc.z += v.z; acc.w += v.w;
    }
    float s = (deg > 0) ? 1.f / (float)deg : 0.f;
    acc.x *= s; acc.y *= s; acc.z *= s; acc.w *= s;
    *(float4*)(Agg + (size_t)w * 128 + lane * 4) = acc;
}

// ======================= final 128->2 projection =======================
__global__ void out_kernel(const float* __restrict__ X, const float* __restrict__ W2,
                           const float* __restrict__ b2, float* __restrict__ out) {
    int gw = (blockIdx.x * blockDim.x + threadIdx.x) >> 5;
    int lane = threadIdx.x & 31;
    if (gw >= NN) return;
    float4 xv = *(const float4*)(X + (size_t)gw * 128 + lane * 4);
    float4 w0 = *(const float4*)(W2 + lane * 4);
    float4 w1 = *(const float4*)(W2 + 128 + lane * 4);
    float s0 = xv.x * w0.x + xv.y * w0.y + xv.z * w0.z + xv.w * w0.w;
    float s1 = xv.x * w1.x + xv.y * w1.y + xv.z * w1.z + xv.w * w1.w;
#pragma unroll
    for (int off = 16; off; off >>= 1) {
        s0 += __shfl_xor_sync(0xffffffffu, s0, off);
        s1 += __shfl_xor_sync(0xffffffffu, s1, off);
    }
    if (lane == 0) {
        out[(size_t)gw * 2 + 0] = s0 + b2[0];
        out[(size_t)gw * 2 + 1] = s1 + b2[1];
    }
}

// ---------------------------------------------------------------------------
extern "C" void kernel_launch(void* const* d_in, const int* in_sizes, int n_in,
                              void* d_out, int out_size) {
    const float* des   = (const float*)d_in[0];
    const float* tweet = (const float*)d_in[1];
    const float* nump  = (const float*)d_in[2];
    const float* catp  = (const float*)d_in[3];
    const int*   ei    = (const int*)d_in[4];
    const int*   et    = (const int*)d_in[5];
    const float* Wd  = (const float*)d_in[6];  const float* bd  = (const float*)d_in[7];
    const float* Wn  = (const float*)d_in[8];  const float* bn  = (const float*)d_in[9];
    const float* Wc  = (const float*)d_in[10]; const float* bc  = (const float*)d_in[11];
    const float* Wt  = (const float*)d_in[12]; const float* bt  = (const float*)d_in[13];
    const float* Win = (const float*)d_in[14]; const float* bin = (const float*)d_in[15];
    const float* rw    = (const float*)d_in[16];
    const float* rroot = (const float*)d_in[17];
    const float* rbias = (const float*)d_in[18];
    const float* Wo1 = (const float*)d_in[19]; const float* bo1 = (const float*)d_in[20];
    const float* Wo2 = (const float*)d_in[21]; const float* bo2 = (const float*)d_in[22];
    float* out = (float*)d_out;

    float *pA, *pB, *pAgg, *pBiasU;
    int *pCnt, *pOff, *pCur, *pBsum, *pEsrc;
    __nv_bfloat16 *pBh, *pBl;
    cudaGetSymbolAddress((void**)&pA, g_bufA);
    cudaGetSymbolAddress((void**)&pB, g_bufB);
    cudaGetSymbolAddress((void**)&pAgg, g_agg);
    cudaGetSymbolAddress((void**)&pCnt, g_cnt);
    cudaGetSymbolAddress((void**)&pOff, g_off);
    cudaGetSymbolAddress((void**)&pCur, g_cur);
    cudaGetSymbolAddress((void**)&pBsum, g_bsum);
    cudaGetSymbolAddress((void**)&pEsrc, g_esrc);
    cudaGetSymbolAddress((void**)&pBh, g_Bh);
    cudaGetSymbolAddress((void**)&pBl, g_Bl);
    cudaGetSymbolAddress((void**)&pBiasU, g_biasU);

    cudaFuncSetAttribute(mma_gemm<1, 1>, cudaFuncAttributeMaxDynamicSharedMemorySize, GEMM_SMEM);
    cudaFuncSetAttribute(mma_gemm<3, 0>, cudaFuncAttributeMaxDynamicSharedMemorySize, GEMM_SMEM);

    const int GU = (NU + 127) / 128;   // 782
    const int GN = (NN + 127) / 128;   // 1563
    const int SCAN_NB = (NSLOT + SCAN_BS - 1) / SCAN_BS;  // 782 (<=1024)

    // 1-2: pack inputs -> B ; pre-convert weights
    pack_kernel<<<(NN * 128 + 255) / 256, 256>>>(des, tweet, nump, catp, pB);
    prep_B_kernel<<<(BTOT + 128 + 255) / 256, 256>>>(Wd, bd, Wn, bn, Wc, bc, Wt, Win,
                                                     rroot, rw, Wo1);
    // 3-5: feature MLP GEMMs -> A ; x = lrelu(x @ W_in^T + b_in): A -> B
    mma_gemm<1, 1><<<GU, 256, GEMM_SMEM>>>(pB, nullptr, pBh, pBl, pBiasU, pA, NU);
    mma_gemm<1, 1><<<GU, 256, GEMM_SMEM>>>(pB + (size_t)NU * 128, nullptr,
                                           pBh + 16384, pBl + 16384, bt,
                                           pA + (size_t)NU * 128, NU);
    mma_gemm<1, 1><<<GN, 256, GEMM_SMEM>>>(pA, nullptr, pBh + 32768, pBl + 32768,
                                           bin, pB, NN);
    // 6-11: CSR build (once; reused by both convs)
    zero2_kernel<<<(NSLOT + 255) / 256, 256>>>(pCnt, pCur, NSLOT);
    count_kernel<<<(NE + 255) / 256, 256>>>(ei, et, pCnt);
    scan1_kernel<<<SCAN_NB, SCAN_BS>>>(pCnt, pOff, pBsum, NSLOT);
    scan2_kernel<<<1, 1024>>>(pBsum, SCAN_NB);
    scan3_kernel<<<SCAN_NB, SCAN_BS>>>(pOff, pBsum, NSLOT);
    fill_kernel<<<(NE + 255) / 256, 256>>>(ei, et, pOff, pCur, pEsrc);

    // conv1: B -> A
    agg_kernel<<<NSLOT / 8, 256>>>(pB, pOff, pCnt, pEsrc, pAgg);
    mma_gemm<3, 0><<<GN, 256, GEMM_SMEM>>>(pB, pAgg, pBh + 49152, pBl + 49152,
                                           rbias, pA, NN);
    // conv2: A -> B
    agg_kernel<<<NSLOT / 8, 256>>>(pA, pOff, pCnt, pEsrc, pAgg);
    mma_gemm<3, 0><<<GN, 256, GEMM_SMEM>>>(pA, pAgg, pBh + 49152, pBl + 49152,
                                           rbias, pB, NN);
    // x = lrelu(x @ W_o1^T + b_o1): B -> A
    mma_gemm<1, 1><<<GN, 256, GEMM_SMEM>>>(pB, nullptr, pBh + 98304, pBl + 98304,
                                           bo1, pA, NN);
    // out = x @ W_o2^T + b_o2
    out_kernel<<<NN / 8, 256>>>(pA, Wo2, bo2, out);
}

// round 6
// speedup vs baseline: 4.5255x; 1.1123x over previous
#include <cuda_runtime.h>
#include <cuda_bf16.h>
#include <cstdint>

#define NU 100000
#define NT 100000
#define NN 200000
#define NE 600000
#define NSLOT (2 * NN)

// ---- scratch (device globals; no runtime allocation) ----
__device__ float g_bufA[(size_t)NN * 128];
__device__ float g_bufB[(size_t)NN * 128];
__device__ float g_agg[(size_t)2 * NN * 128];
// CSR structures
__device__ int g_cnt[NSLOT];
__device__ int g_off[NSLOT];
__device__ int g_cur[NSLOT];
__device__ int g_bsum[1024];
__device__ int g_esrc[NE];
// pre-converted weights, bf16 hi/lo, [N=128, Ktot] K-major rows:
// featU @0 (Ktot128), featT @16384, lin @32768, conv @49152 (Ktot384), o1 @98304
#define BTOT 114688
__device__ __align__(16) __nv_bfloat16 g_Bh[BTOT];
__device__ __align__(16) __nv_bfloat16 g_Bl[BTOT];
__device__ float g_biasU[128];

__device__ __forceinline__ float lrelu(float x) { return x > 0.f ? x : 0.01f * x; }

// ======================= PTX helpers (portable sm_80+) =======================
__device__ __forceinline__ uint32_t smem_to_u32(const void* p) {
    uint32_t a;
    asm("{ .reg .u64 t; cvta.to.shared.u64 t, %1; cvt.u32.u64 %0, t; }" : "=r"(a) : "l"(p));
    return a;
}
__device__ __forceinline__ void ldsm_x4(uint32_t& r0, uint32_t& r1, uint32_t& r2,
                                        uint32_t& r3, uint32_t a) {
    asm volatile("ldmatrix.sync.aligned.m8n8.x4.shared.b16 {%0,%1,%2,%3}, [%4];"
                 : "=r"(r0), "=r"(r1), "=r"(r2), "=r"(r3) : "r"(a));
}
__device__ __forceinline__ void ldsm_x2(uint32_t& r0, uint32_t& r1, uint32_t a) {
    asm volatile("ldmatrix.sync.aligned.m8n8.x2.shared.b16 {%0,%1}, [%2];"
                 : "=r"(r0), "=r"(r1) : "r"(a));
}
__device__ __forceinline__ void mma16816(float* d, uint32_t a0, uint32_t a1, uint32_t a2,
                                         uint32_t a3, uint32_t b0, uint32_t b1) {
    asm volatile(
        "mma.sync.aligned.m16n8k16.row.col.f32.bf16.bf16.f32 "
        "{%0,%1,%2,%3}, {%4,%5,%6,%7}, {%8,%9}, {%0,%1,%2,%3};"
        : "+f"(d[0]), "+f"(d[1]), "+f"(d[2]), "+f"(d[3])
        : "r"(a0), "r"(a1), "r"(a2), "r"(a3), "r"(b0), "r"(b1));
}
#define CP_ASYNC16(dst, src) \
    asm volatile("cp.async.ca.shared.global [%0], [%1], 16;" :: "r"(dst), "l"(src))
#define CP_COMMIT() asm volatile("cp.async.commit_group;" ::: "memory")
#define CP_WAIT0() asm volatile("cp.async.wait_group 0;" ::: "memory")

__device__ __forceinline__ uint32_t pk2(float a, float b) {
    __nv_bfloat16 ha = __float2bfloat16(a), hb = __float2bfloat16(b);
    return (uint32_t)__bfloat16_as_ushort(ha) | ((uint32_t)__bfloat16_as_ushort(hb) << 16);
}

// ======================= bf16x2 warp-MMA GEMM =======================
// C[M,128] = act( sum_seg A_seg[M,128] @ B_seg^T + bias )
// Block 256 thr, tile 128x128, warp tile 64x32, BK=32, double-buffered smem.
// __launch_bounds__(256,2): cap regs at 128 so 2 CTAs/SM fit the register file.
#define ASTR 40
#define AH_OFF 0
#define AL_OFF 5120
#define BH_OFF 10240
#define BL_OFF 15360
#define BUF_ELE 20480
#define GEMM_SMEM (2 * BUF_ELE * 2)

template <int NSEG, int RELU>
__global__ void __launch_bounds__(256, 2) mma_gemm(
    const float* __restrict__ X, const float* __restrict__ Agg,
    const __nv_bfloat16* __restrict__ Bh, const __nv_bfloat16* __restrict__ Bl,
    const float* __restrict__ bias, float* __restrict__ C, int M) {
    extern __shared__ __nv_bfloat16 sm[];
    const int KTOT = NSEG * 128;
    const int CHUNKS = NSEG * 4;
    int tid = threadIdx.x, lane = tid & 31, wid = tid >> 5;
    int warpM = wid & 1, warpN = wid >> 1;
    int rowBlock = blockIdx.x * 128;
    uint32_t smb = smem_to_u32(sm);

    int arow = tid >> 1, ahalf = tid & 1;
    int grow = rowBlock + arow;
    bool rok = grow < M;

    float acc[4][4][4];
#pragma unroll
    for (int i = 0; i < 4; i++)
#pragma unroll
        for (int j = 0; j < 4; j++)
#pragma unroll
            for (int k = 0; k < 4; k++) acc[i][j][k] = 0.f;

    float4 ar[4];

    // ---- prologue: stage chunk 0 into buf 0 ----
    {
        const float* p = X + (size_t)grow * 128 + ahalf * 16;
#pragma unroll
        for (int i = 0; i < 4; i++)
            ar[i] = rok ? *(const float4*)(p + i * 4) : make_float4(0.f, 0.f, 0.f, 0.f);
        const __nv_bfloat16* bh = Bh + (size_t)arow * KTOT + ahalf * 16;
        const __nv_bfloat16* bl = Bl + (size_t)arow * KTOT + ahalf * 16;
        uint32_t dH = smb + (uint32_t)(BH_OFF + arow * ASTR + ahalf * 16) * 2;
        uint32_t dL = smb + (uint32_t)(BL_OFF + arow * ASTR + ahalf * 16) * 2;
        CP_ASYNC16(dH, bh); CP_ASYNC16(dH + 16, bh + 8);
        CP_ASYNC16(dL, bl); CP_ASYNC16(dL + 16, bl + 8);
        CP_COMMIT();
        __nv_bfloat16* dh = sm + AH_OFF + arow * ASTR + ahalf * 16;
        __nv_bfloat16* dl = sm + AL_OFF + arow * ASTR + ahalf * 16;
#pragma unroll
        for (int i = 0; i < 4; i++) {
            float4 v = ar[i];
            __nv_bfloat16 hx = __float2bfloat16(v.x), hy = __float2bfloat16(v.y);
            __nv_bfloat16 hz = __float2bfloat16(v.z), hw = __float2bfloat16(v.w);
            uint2 hu = make_uint2(
                (uint32_t)__bfloat16_as_ushort(hx) | ((uint32_t)__bfloat16_as_ushort(hy) << 16),
                (uint32_t)__bfloat16_as_ushort(hz) | ((uint32_t)__bfloat16_as_ushort(hw) << 16));
            uint2 lu = make_uint2(pk2(v.x - __bfloat162float(hx), v.y - __bfloat162float(hy)),
                                  pk2(v.z - __bfloat162float(hz), v.w - __bfloat162float(hw)));
            *(uint2*)(dh + i * 4) = hu;
            *(uint2*)(dl + i * 4) = lu;
        }
    }
    CP_WAIT0();
    __syncthreads();

    int lr8 = lane & 7, lb = lane >> 3, l16 = lane & 15;

    for (int c = 0; c < CHUNKS; c++) {
        int buf = c & 1;
        uint32_t base = smb + (uint32_t)buf * BUF_ELE * 2;
        bool hasNext = (c + 1) < CHUNKS;

        if (hasNext) {
            int cn = c + 1;
            int seg = cn >> 2, kin = (cn & 3) * 32;
            const __nv_bfloat16* bh = Bh + (size_t)arow * KTOT + cn * 32 + ahalf * 16;
            const __nv_bfloat16* bl = Bl + (size_t)arow * KTOT + cn * 32 + ahalf * 16;
            uint32_t off = (uint32_t)((buf ^ 1) * BUF_ELE + arow * ASTR + ahalf * 16) * 2;
            uint32_t dH = smb + off + BH_OFF * 2;
            uint32_t dL = smb + off + BL_OFF * 2;
            CP_ASYNC16(dH, bh); CP_ASYNC16(dH + 16, bh + 8);
            CP_ASYNC16(dL, bl); CP_ASYNC16(dL + 16, bl + 8);
            CP_COMMIT();
            const float* Ap = (seg == 0) ? X : Agg + (size_t)(seg - 1) * NN * 128;
            const float* p = Ap + (size_t)grow * 128 + kin + ahalf * 16;
#pragma unroll
            for (int i = 0; i < 4; i++)
                ar[i] = rok ? *(const float4*)(p + i * 4) : make_float4(0.f, 0.f, 0.f, 0.f);
        }

        // ---- MMA on current buffer ----
        {
            uint32_t aH = base + AH_OFF * 2, aL = base + AL_OFF * 2;
            uint32_t bH = base + BH_OFF * 2, bL = base + BL_OFF * 2;
#pragma unroll
            for (int ks = 0; ks < 2; ks++) {
                uint32_t bhf[4][2], blf[4][2];
                int bCol = ks * 16 + (l16 >> 3) * 8;
#pragma unroll
                for (int ni = 0; ni < 4; ni++) {
                    int bRow = warpN * 32 + ni * 8 + (l16 & 7);
                    uint32_t o = (uint32_t)(bRow * ASTR + bCol) * 2;
                    ldsm_x2(bhf[ni][0], bhf[ni][1], bH + o);
                    ldsm_x2(blf[ni][0], blf[ni][1], bL + o);
                }
                int aCol = ks * 16 + (lb >> 1) * 8;
#pragma unroll
                for (int mi = 0; mi < 4; mi++) {
                    int aRow = warpM * 64 + mi * 16 + (lb & 1) * 8 + lr8;
                    uint32_t o = (uint32_t)(aRow * ASTR + aCol) * 2;
                    uint32_t a0, a1, a2, a3, q0, q1, q2, q3;
                    ldsm_x4(a0, a1, a2, a3, aH + o);
                    ldsm_x4(q0, q1, q2, q3, aL + o);
#pragma unroll
                    for (int ni = 0; ni < 4; ni++) {
                        mma16816(acc[mi][ni], a0, a1, a2, a3, bhf[ni][0], bhf[ni][1]);
                        mma16816(acc[mi][ni], a0, a1, a2, a3, blf[ni][0], blf[ni][1]);
                        mma16816(acc[mi][ni], q0, q1, q2, q3, bhf[ni][0], bhf[ni][1]);
                    }
                }
            }
        }

        if (hasNext) {
            __nv_bfloat16* dh = sm + (buf ^ 1) * BUF_ELE + AH_OFF + arow * ASTR + ahalf * 16;
            __nv_bfloat16* dl = sm + (buf ^ 1) * BUF_ELE + AL_OFF + arow * ASTR + ahalf * 16;
#pragma unroll
            for (int i = 0; i < 4; i++) {
                float4 v = ar[i];
                __nv_bfloat16 hx = __float2bfloat16(v.x), hy = __float2bfloat16(v.y);
                __nv_bfloat16 hz = __float2bfloat16(v.z), hw = __float2bfloat16(v.w);
                uint2 hu = make_uint2(
                    (uint32_t)__bfloat16_as_ushort(hx) | ((uint32_t)__bfloat16_as_ushort(hy) << 16),
                    (uint32_t)__bfloat16_as_ushort(hz) | ((uint32_t)__bfloat16_as_ushort(hw) << 16));
                uint2 lu = make_uint2(pk2(v.x - __bfloat162float(hx), v.y - __bfloat162float(hy)),
                                      pk2(v.z - __bfloat162float(hz), v.w - __bfloat162float(hw)));
                *(uint2*)(dh + i * 4) = hu;
                *(uint2*)(dl + i * 4) = lu;
            }
        }
        CP_WAIT0();
        __syncthreads();
    }

    // ---- epilogue ----
    int gid = lane >> 2, qid = lane & 3;
#pragma unroll
    for (int mi = 0; mi < 4; mi++) {
        int r0 = rowBlock + warpM * 64 + mi * 16 + gid;
        int r1 = r0 + 8;
#pragma unroll
        for (int ni = 0; ni < 4; ni++) {
            int cb = warpN * 32 + ni * 8 + qid * 2;
            float b0 = bias[cb], b1 = bias[cb + 1];
            float v0 = acc[mi][ni][0] + b0, v1 = acc[mi][ni][1] + b1;
            float v2 = acc[mi][ni][2] + b0, v3 = acc[mi][ni][3] + b1;
            if (RELU) { v0 = lrelu(v0); v1 = lrelu(v1); v2 = lrelu(v2); v3 = lrelu(v3); }
            if (r0 < M) { float2 t = make_float2(v0, v1); *(float2*)(C + (size_t)r0 * 128 + cb) = t; }
            if (r1 < M) { float2 t = make_float2(v2, v3); *(float2*)(C + (size_t)r1 * 128 + cb) = t; }
        }
    }
}

// ======================= feature packing =======================
__global__ void pack_kernel(const float* __restrict__ des, const float* __restrict__ tweet,
                            const float* __restrict__ nump, const float* __restrict__ catp,
                            float* __restrict__ P) {
    long idx = blockIdx.x * 256L + threadIdx.x;
    if (idx >= (long)NN * 128) return;
    int row = (int)(idx >> 7), col = (int)(idx & 127);
    float v = 0.f;
    if (row < NU) {
        if (col < 100) v = des[(size_t)row * 100 + col];
        else if (col < 106) v = nump[(size_t)row * 6 + (col - 100)];
        else if (col < 117) v = catp[(size_t)row * 11 + (col - 106)];
    } else {
        if (col < 100) v = tweet[(size_t)(row - NU) * 100 + col];
    }
    P[idx] = v;
}

// ======================= weight pre-conversion =======================
__global__ void prep_B_kernel(const float* __restrict__ Wd, const float* __restrict__ bd,
                              const float* __restrict__ Wn, const float* __restrict__ bn,
                              const float* __restrict__ Wc, const float* __restrict__ bc,
                              const float* __restrict__ Wt, const float* __restrict__ Win,
                              const float* __restrict__ root, const float* __restrict__ rw,
                              const float* __restrict__ Wo1) {
    int idx = blockIdx.x * 256 + threadIdx.x;
    if (idx >= BTOT + 128) return;
    if (idx >= BTOT) {
        int n = idx - BTOT;
        g_biasU[n] = (n < 64) ? bd[n] : (n < 96) ? bn[n - 64] : bc[n - 96];
        return;
    }
    float v = 0.f;
    if (idx < 16384) {  // featU blockdiag [n,k=128]
        int n = idx >> 7, k = idx & 127;
        if (n < 64) { if (k < 100) v = Wd[n * 100 + k]; }
        else if (n < 96) { if (k >= 100 && k < 106) v = Wn[(n - 64) * 6 + (k - 100)]; }
        else { if (k >= 106 && k < 117) v = Wc[(n - 96) * 11 + (k - 106)]; }
    } else if (idx < 32768) {  // featT
        int l = idx - 16384;
        int n = l >> 7, k = l & 127;
        if (k < 100) v = Wt[n * 100 + k];
    } else if (idx < 49152) {  // lin
        v = Win[idx - 32768];
    } else if (idx < 98304) {  // conv: [n, k=384]: seg0 root^T, seg1/2 rw^T
        int l = idx - 49152;
        int n = l / 384, k = l % 384;
        if (k < 128) v = root[k * 128 + n];
        else if (k < 256) v = rw[(k - 128) * 128 + n];
        else v = rw[16384 + (k - 256) * 128 + n];
    } else {  // o1
        v = Wo1[idx - 98304];
    }
    __nv_bfloat16 h = __float2bfloat16(v);
    g_Bh[idx] = h;
    g_Bl[idx] = __float2bfloat16(v - __bfloat162float(h));
}

// ======================= CSR build =======================
__global__ void zero2_kernel(int* __restrict__ a, int* __restrict__ b, int n) {
    int i = blockIdx.x * 256 + threadIdx.x;
    if (i < n) { a[i] = 0; b[i] = 0; }
}

__global__ void count_kernel(const int* __restrict__ ei, const int* __restrict__ et,
                             int* __restrict__ cnt) {
    int e = blockIdx.x * 256 + threadIdx.x;
    if (e >= NE) return;
    atomicAdd(&cnt[et[e] * NN + ei[NE + e]], 1);
}

#define SCAN_BS 512
__global__ void scan1_kernel(const int* __restrict__ cnt, int* __restrict__ off,
                             int* __restrict__ bsum, int n) {
    __shared__ int sh[SCAN_BS];
    int t = threadIdx.x;
    int i = blockIdx.x * SCAN_BS + t;
    int v = (i < n) ? cnt[i] : 0;
    sh[t] = v;
    __syncthreads();
#pragma unroll
    for (int d = 1; d < SCAN_BS; d <<= 1) {
        int x = (t >= d) ? sh[t - d] : 0;
        __syncthreads();
        sh[t] += x;
        __syncthreads();
    }
    if (i < n) off[i] = sh[t] - v;  // exclusive within block
    if (t == SCAN_BS - 1) bsum[blockIdx.x] = sh[t];
}

__global__ void scan2_kernel(int* __restrict__ bsum, int nb) {
    __shared__ int sh[1024];
    int t = threadIdx.x;
    int v = (t < nb) ? bsum[t] : 0;
    sh[t] = v;
    __syncthreads();
#pragma unroll
    for (int d = 1; d < 1024; d <<= 1) {
        int x = (t >= d) ? sh[t - d] : 0;
        __syncthreads();
        sh[t] += x;
        __syncthreads();
    }
    if (t < nb) bsum[t] = sh[t] - v;  // exclusive
}

__global__ void scan3_kernel(int* __restrict__ off, const int* __restrict__ bsum, int n) {
    int i = blockIdx.x * SCAN_BS + threadIdx.x;
    if (i < n) off[i] += bsum[blockIdx.x];
}

__global__ void fill_kernel(const int* __restrict__ ei, const int* __restrict__ et,
                            const int* __restrict__ off, int* __restrict__ cur,
                            int* __restrict__ esrc) {
    int e = blockIdx.x * 256 + threadIdx.x;
    if (e >= NE) return;
    int slot = et[e] * NN + ei[NE + e];
    int pos = off[slot] + atomicAdd(&cur[slot], 1);
    esrc[pos] = ei[e];
}

// ======================= CSR gather-mean aggregation =======================
__global__ void agg_kernel(const float* __restrict__ X, const int* __restrict__ off,
                           const int* __restrict__ cnt, const int* __restrict__ esrc,
                           float* __restrict__ Agg) {
    int w = (blockIdx.x * blockDim.x + threadIdx.x) >> 5;
    int lane = threadIdx.x & 31;
    if (w >= NSLOT) return;
    int beg = off[w], deg = cnt[w];
    float4 acc = make_float4(0.f, 0.f, 0.f, 0.f);
    for (int i = 0; i < deg; i++) {
        int src = __ldg(&esrc[beg + i]);
        float4 v = *(const float4*)(X + (size_t)src * 128 + lane * 4);
        acc.x += v.x; acc.y += v.y; acc.z += v.z; acc.w += v.w;
    }
    float s = (deg > 0) ? 1.f / (float)deg : 0.f;
    acc.x *= s; acc.y *= s; acc.z *= s; acc.w *= s;
    *(float4*)(Agg + (size_t)w * 128 + lane * 4) = acc;
}

// ======================= final 128->2 projection =======================
__global__ void out_kernel(const float* __restrict__ X, const float* __restrict__ W2,
                           const float* __restrict__ b2, float* __restrict__ out) {
    int gw = (blockIdx.x * blockDim.x + threadIdx.x) >> 5;
    int lane = threadIdx.x & 31;
    if (gw >= NN) return;
    float4 xv = *(const float4*)(X + (size_t)gw * 128 + lane * 4);
    float4 w0 = *(const float4*)(W2 + lane * 4);
    float4 w1 = *(const float4*)(W2 + 128 + lane * 4);
    float s0 = xv.x * w0.x + xv.y * w0.y + xv.z * w0.z + xv.w * w0.w;
    float s1 = xv.x * w1.x + xv.y * w1.y + xv.z * w1.z + xv.w * w1.w;
#pragma unroll
    for (int off = 16; off; off >>= 1) {
        s0 += __shfl_xor_sync(0xffffffffu, s0, off);
        s1 += __shfl_xor_sync(0xffffffffu, s1, off);
    }
    if (lane == 0) {
        out[(size_t)gw * 2 + 0] = s0 + b2[0];
        out[(size_t)gw * 2 + 1] = s1 + b2[1];
    }
}

// ---------------------------------------------------------------------------
extern "C" void kernel_launch(void* const* d_in, const int* in_sizes, int n_in,
                              void* d_out, int out_size) {
    const float* des   = (const float*)d_in[0];
    const float* tweet = (const float*)d_in[1];
    const float* nump  = (const float*)d_in[2];
    const float* catp  = (const float*)d_in[3];
    const int*   ei    = (const int*)d_in[4];
    const int*   et    = (const int*)d_in[5];
    const float* Wd  = (const float*)d_in[6];  const float* bd  = (const float*)d_in[7];
    const float* Wn  = (const float*)d_in[8];  const float* bn  = (const float*)d_in[9];
    const float* Wc  = (const float*)d_in[10]; const float* bc  = (const float*)d_in[11];
    const float* Wt  = (const float*)d_in[12]; const float* bt  = (const float*)d_in[13];
    const float* Win = (const float*)d_in[14]; const float* bin = (const float*)d_in[15];
    const float* rw    = (const float*)d_in[16];
    const float* rroot = (const float*)d_in[17];
    const float* rbias = (const float*)d_in[18];
    const float* Wo1 = (const float*)d_in[19]; const float* bo1 = (const float*)d_in[20];
    const float* Wo2 = (const float*)d_in[21]; const float* bo2 = (const float*)d_in[22];
    float* out = (float*)d_out;

    float *pA, *pB, *pAgg, *pBiasU;
    int *pCnt, *pOff, *pCur, *pBsum, *pEsrc;
    __nv_bfloat16 *pBh, *pBl;
    cudaGetSymbolAddress((void**)&pA, g_bufA);
    cudaGetSymbolAddress((void**)&pB, g_bufB);
    cudaGetSymbolAddress((void**)&pAgg, g_agg);
    cudaGetSymbolAddress((void**)&pCnt, g_cnt);
    cudaGetSymbolAddress((void**)&pOff, g_off);
    cudaGetSymbolAddress((void**)&pCur, g_cur);
    cudaGetSymbolAddress((void**)&pBsum, g_bsum);
    cudaGetSymbolAddress((void**)&pEsrc, g_esrc);
    cudaGetSymbolAddress((void**)&pBh, g_Bh);
    cudaGetSymbolAddress((void**)&pBl, g_Bl);
    cudaGetSymbolAddress((void**)&pBiasU, g_biasU);

    cudaFuncSetAttribute(mma_gemm<1, 1>, cudaFuncAttributeMaxDynamicSharedMemorySize, GEMM_SMEM);
    cudaFuncSetAttribute(mma_gemm<3, 0>, cudaFuncAttributeMaxDynamicSharedMemorySize, GEMM_SMEM);

    const int GU = (NU + 127) / 128;   // 782
    const int GN = (NN + 127) / 128;   // 1563
    const int SCAN_NB = (NSLOT + SCAN_BS - 1) / SCAN_BS;  // 782 (<=1024)

    // 1-2: pack inputs -> B ; pre-convert weights
    pack_kernel<<<(NN * 128 + 255) / 256, 256>>>(des, tweet, nump, catp, pB);
    prep_B_kernel<<<(BTOT + 128 + 255) / 256, 256>>>(Wd, bd, Wn, bn, Wc, bc, Wt, Win,
                                                     rroot, rw, Wo1);
    // 3-5: feature MLP GEMMs -> A ; x = lrelu(x @ W_in^T + b_in): A -> B
    mma_gemm<1, 1><<<GU, 256, GEMM_SMEM>>>(pB, nullptr, pBh, pBl, pBiasU, pA, NU);
    mma_gemm<1, 1><<<GU, 256, GEMM_SMEM>>>(pB + (size_t)NU * 128, nullptr,
                                           pBh + 16384, pBl + 16384, bt,
                                           pA + (size_t)NU * 128, NU);
    mma_gemm<1, 1><<<GN, 256, GEMM_SMEM>>>(pA, nullptr, pBh + 32768, pBl + 32768,
                                           bin, pB, NN);
    // 6-11: CSR build (once; reused by both convs)
    zero2_kernel<<<(NSLOT + 255) / 256, 256>>>(pCnt, pCur, NSLOT);
    count_kernel<<<(NE + 255) / 256, 256>>>(ei, et, pCnt);
    scan1_kernel<<<SCAN_NB, SCAN_BS>>>(pCnt, pOff, pBsum, NSLOT);
    scan2_kernel<<<1, 1024>>>(pBsum, SCAN_NB);
    scan3_kernel<<<SCAN_NB, SCAN_BS>>>(pOff, pBsum, NSLOT);
    fill_kernel<<<(NE + 255) / 256, 256>>>(ei, et, pOff, pCur, pEsrc);

    // conv1: B -> A
    agg_kernel<<<NSLOT / 8, 256>>>(pB, pOff, pCnt, pEsrc, pAgg);
    mma_gemm<3, 0><<<GN, 256, GEMM_SMEM>>>(pB, pAgg, pBh + 49152, pBl + 49152,
                                           rbias, pA, NN);
    // conv2: A -> B
    agg_kernel<<<NSLOT / 8, 256>>>(pA, pOff, pCnt, pEsrc, pAgg);
    mma_gemm<3, 0><<<GN, 256, GEMM_SMEM>>>(pA, pAgg, pBh + 49152, pBl + 49152,
                                           rbias, pB, NN);
    // x = lrelu(x @ W_o1^T + b_o1): B -> A
    mma_gemm<1, 1><<<GN, 256, GEMM_SMEM>>>(pB, nullptr, pBh + 98304, pBl + 98304,
                                           bo1, pA, NN);
    // out = x @ W_o2^T + b_o2
    out_kernel<<<NN / 8, 256>>>(pA, Wo2, bo2, out);
}

// round 7
// speedup vs baseline: 5.4189x; 1.1974x over previous
#include <cuda_runtime.h>
#include <cuda_fp16.h>
#include <cuda_bf16.h>
#include <cstdint>

#define NU 100000
#define NT 100000
#define NN 200000
#define NE 600000
#define NSLOT (2 * NN)

// ---- scratch (device globals; no runtime allocation) ----
__device__ float g_bufA[(size_t)NN * 128];
__device__ float g_bufB[(size_t)NN * 128];
__device__ float g_agg[(size_t)2 * NN * 128];
// CSR structures
__device__ int g_cnt[NSLOT];
__device__ int g_off[NSLOT];
__device__ int g_cur[NSLOT];
__device__ int g_bsum[1024];
__device__ int g_esrc[NE];
// pre-converted weights, fp16, [N=128, Ktot] K-major rows:
// featU @0 (Ktot128), featT @16384, lin @32768, conv @49152 (Ktot384), o1 @98304
#define BTOT 114688
__device__ __align__(16) __half g_Bh[BTOT];
__device__ float g_biasU[128];

__device__ __forceinline__ float lrelu(float x) { return x > 0.f ? x : 0.01f * x; }

// ======================= PTX helpers (portable sm_80+) =======================
__device__ __forceinline__ uint32_t smem_to_u32(const void* p) {
    uint32_t a;
    asm("{ .reg .u64 t; cvta.to.shared.u64 t, %1; cvt.u32.u64 %0, t; }" : "=r"(a) : "l"(p));
    return a;
}
__device__ __forceinline__ void ldsm_x4(uint32_t& r0, uint32_t& r1, uint32_t& r2,
                                        uint32_t& r3, uint32_t a) {
    asm volatile("ldmatrix.sync.aligned.m8n8.x4.shared.b16 {%0,%1,%2,%3}, [%4];"
                 : "=r"(r0), "=r"(r1), "=r"(r2), "=r"(r3) : "r"(a));
}
__device__ __forceinline__ void ldsm_x2(uint32_t& r0, uint32_t& r1, uint32_t a) {
    asm volatile("ldmatrix.sync.aligned.m8n8.x2.shared.b16 {%0,%1}, [%2];"
                 : "=r"(r0), "=r"(r1) : "r"(a));
}
__device__ __forceinline__ void mma16816(float* d, uint32_t a0, uint32_t a1, uint32_t a2,
                                         uint32_t a3, uint32_t b0, uint32_t b1) {
    asm volatile(
        "mma.sync.aligned.m16n8k16.row.col.f32.f16.f16.f32 "
        "{%0,%1,%2,%3}, {%4,%5,%6,%7}, {%8,%9}, {%0,%1,%2,%3};"
        : "+f"(d[0]), "+f"(d[1]), "+f"(d[2]), "+f"(d[3])
        : "r"(a0), "r"(a1), "r"(a2), "r"(a3), "r"(b0), "r"(b1));
}
#define CP_ASYNC16(dst, src) \
    asm volatile("cp.async.ca.shared.global [%0], [%1], 16;" :: "r"(dst), "l"(src))
#define CP_COMMIT() asm volatile("cp.async.commit_group;" ::: "memory")
#define CP_WAIT0() asm volatile("cp.async.wait_group 0;" ::: "memory")

__device__ __forceinline__ uint32_t pk2h(float a, float b) {
    __half2 h = __floats2half2_rn(a, b);
    return *(uint32_t*)&h;
}

// ======================= fp16 2-product warp-MMA GEMM =======================
// C[M,128] = act( sum_seg A_seg[M,128] @ B_seg^T + bias )
// A = Ah + Al (both fp16, A exact to ~2^-22); B rounded once to fp16.
// C ≈ Ah·Bh + Al·Bh  (2 MMAs per k-step; dropped term ~2^-11 rel on B)
// Block 256 thr, tile 128x128, warp tile 64x32, BK=32, double-buffered smem.
#define ASTR 40
#define AH_OFF 0
#define AL_OFF 5120
#define BH_OFF 10240
#define BUF_ELE 15360
#define GEMM_SMEM (2 * BUF_ELE * 2)

template <int NSEG, int RELU>
__global__ void __launch_bounds__(256, 2) mma_gemm(
    const float* __restrict__ X, const float* __restrict__ Agg,
    const __half* __restrict__ Bh,
    const float* __restrict__ bias, float* __restrict__ C, int M) {
    extern __shared__ __half sm[];
    const int KTOT = NSEG * 128;
    const int CHUNKS = NSEG * 4;
    int tid = threadIdx.x, lane = tid & 31, wid = tid >> 5;
    int warpM = wid & 1, warpN = wid >> 1;
    int rowBlock = blockIdx.x * 128;
    uint32_t smb = smem_to_u32(sm);

    int arow = tid >> 1, ahalf = tid & 1;
    int grow = rowBlock + arow;
    bool rok = grow < M;

    float acc[4][4][4];
#pragma unroll
    for (int i = 0; i < 4; i++)
#pragma unroll
        for (int j = 0; j < 4; j++)
#pragma unroll
            for (int k = 0; k < 4; k++) acc[i][j][k] = 0.f;

    float4 ar[4];

    // ---- prologue: stage chunk 0 into buf 0 ----
    {
        const float* p = X + (size_t)grow * 128 + ahalf * 16;
#pragma unroll
        for (int i = 0; i < 4; i++)
            ar[i] = rok ? *(const float4*)(p + i * 4) : make_float4(0.f, 0.f, 0.f, 0.f);
        const __half* bh = Bh + (size_t)arow * KTOT + ahalf * 16;
        uint32_t dH = smb + (uint32_t)(BH_OFF + arow * ASTR + ahalf * 16) * 2;
        CP_ASYNC16(dH, bh); CP_ASYNC16(dH + 16, bh + 8);
        CP_COMMIT();
        __half* dh = sm + AH_OFF + arow * ASTR + ahalf * 16;
        __half* dl = sm + AL_OFF + arow * ASTR + ahalf * 16;
#pragma unroll
        for (int i = 0; i < 4; i++) {
            float4 v = ar[i];
            __half hx = __float2half_rn(v.x), hy = __float2half_rn(v.y);
            __half hz = __float2half_rn(v.z), hw = __float2half_rn(v.w);
            uint2 hu = make_uint2(
                (uint32_t)__half_as_ushort(hx) | ((uint32_t)__half_as_ushort(hy) << 16),
                (uint32_t)__half_as_ushort(hz) | ((uint32_t)__half_as_ushort(hw) << 16));
            uint2 lu = make_uint2(pk2h(v.x - __half2float(hx), v.y - __half2float(hy)),
                                  pk2h(v.z - __half2float(hz), v.w - __half2float(hw)));
            *(uint2*)(dh + i * 4) = hu;
            *(uint2*)(dl + i * 4) = lu;
        }
    }
    CP_WAIT0();
    __syncthreads();

    int lr8 = lane & 7, lb = lane >> 3, l16 = lane & 15;

    for (int c = 0; c < CHUNKS; c++) {
        int buf = c & 1;
        uint32_t base = smb + (uint32_t)buf * BUF_ELE * 2;
        bool hasNext = (c + 1) < CHUNKS;

        if (hasNext) {
            int cn = c + 1;
            int seg = cn >> 2, kin = (cn & 3) * 32;
            const __half* bh = Bh + (size_t)arow * KTOT + cn * 32 + ahalf * 16;
            uint32_t dH = smb + (uint32_t)((buf ^ 1) * BUF_ELE + BH_OFF + arow * ASTR + ahalf * 16) * 2;
            CP_ASYNC16(dH, bh); CP_ASYNC16(dH + 16, bh + 8);
            CP_COMMIT();
            const float* Ap = (seg == 0) ? X : Agg + (size_t)(seg - 1) * NN * 128;
            const float* p = Ap + (size_t)grow * 128 + kin + ahalf * 16;
#pragma unroll
            for (int i = 0; i < 4; i++)
                ar[i] = rok ? *(const float4*)(p + i * 4) : make_float4(0.f, 0.f, 0.f, 0.f);
        }

        // ---- MMA on current buffer ----
        {
            uint32_t aH = base + AH_OFF * 2, aL = base + AL_OFF * 2;
            uint32_t bH = base + BH_OFF * 2;
#pragma unroll
            for (int ks = 0; ks < 2; ks++) {
                uint32_t bhf[4][2];
                int bCol = ks * 16 + (l16 >> 3) * 8;
#pragma unroll
                for (int ni = 0; ni < 4; ni++) {
                    int bRow = warpN * 32 + ni * 8 + (l16 & 7);
                    uint32_t o = (uint32_t)(bRow * ASTR + bCol) * 2;
                    ldsm_x2(bhf[ni][0], bhf[ni][1], bH + o);
                }
                int aCol = ks * 16 + (lb >> 1) * 8;
#pragma unroll
                for (int mi = 0; mi < 4; mi++) {
                    int aRow = warpM * 64 + mi * 16 + (lb & 1) * 8 + lr8;
                    uint32_t o = (uint32_t)(aRow * ASTR + aCol) * 2;
                    uint32_t a0, a1, a2, a3, q0, q1, q2, q3;
                    ldsm_x4(a0, a1, a2, a3, aH + o);
                    ldsm_x4(q0, q1, q2, q3, aL + o);
#pragma unroll
                    for (int ni = 0; ni < 4; ni++) {
                        mma16816(acc[mi][ni], a0, a1, a2, a3, bhf[ni][0], bhf[ni][1]);
                        mma16816(acc[mi][ni], q0, q1, q2, q3, bhf[ni][0], bhf[ni][1]);
                    }
                }
            }
        }

        if (hasNext) {
            __half* dh = sm + (buf ^ 1) * BUF_ELE + AH_OFF + arow * ASTR + ahalf * 16;
            __half* dl = sm + (buf ^ 1) * BUF_ELE + AL_OFF + arow * ASTR + ahalf * 16;
#pragma unroll
            for (int i = 0; i < 4; i++) {
                float4 v = ar[i];
                __half hx = __float2half_rn(v.x), hy = __float2half_rn(v.y);
                __half hz = __float2half_rn(v.z), hw = __float2half_rn(v.w);
                uint2 hu = make_uint2(
                    (uint32_t)__half_as_ushort(hx) | ((uint32_t)__half_as_ushort(hy) << 16),
                    (uint32_t)__half_as_ushort(hz) | ((uint32_t)__half_as_ushort(hw) << 16));
                uint2 lu = make_uint2(pk2h(v.x - __half2float(hx), v.y - __half2float(hy)),
                                      pk2h(v.z - __half2float(hz), v.w - __half2float(hw)));
                *(uint2*)(dh + i * 4) = hu;
                *(uint2*)(dl + i * 4) = lu;
            }
        }
        CP_WAIT0();
        __syncthreads();
    }

    // ---- epilogue ----
    int gid = lane >> 2, qid = lane & 3;
#pragma unroll
    for (int mi = 0; mi < 4; mi++) {
        int r0 = rowBlock + warpM * 64 + mi * 16 + gid;
        int r1 = r0 + 8;
#pragma unroll
        for (int ni = 0; ni < 4; ni++) {
            int cb = warpN * 32 + ni * 8 + qid * 2;
            float b0 = bias[cb], b1 = bias[cb + 1];
            float v0 = acc[mi][ni][0] + b0, v1 = acc[mi][ni][1] + b1;
            float v2 = acc[mi][ni][2] + b0, v3 = acc[mi][ni][3] + b1;
            if (RELU) { v0 = lrelu(v0); v1 = lrelu(v1); v2 = lrelu(v2); v3 = lrelu(v3); }
            if (r0 < M) { float2 t = make_float2(v0, v1); *(float2*)(C + (size_t)r0 * 128 + cb) = t; }
            if (r1 < M) { float2 t = make_float2(v2, v3); *(float2*)(C + (size_t)r1 * 128 + cb) = t; }
        }
    }
}

// ======================= feature packing =======================
__global__ void pack_kernel(const float* __restrict__ des, const float* __restrict__ tweet,
                            const float* __restrict__ nump, const float* __restrict__ catp,
                            float* __restrict__ P) {
    long idx = blockIdx.x * 256L + threadIdx.x;
    if (idx >= (long)NN * 128) return;
    int row = (int)(idx >> 7), col = (int)(idx & 127);
    float v = 0.f;
    if (row < NU) {
        if (col < 100) v = des[(size_t)row * 100 + col];
        else if (col < 106) v = nump[(size_t)row * 6 + (col - 100)];
        else if (col < 117) v = catp[(size_t)row * 11 + (col - 106)];
    } else {
        if (col < 100) v = tweet[(size_t)(row - NU) * 100 + col];
    }
    P[idx] = v;
}

// ======================= weight pre-conversion =======================
__global__ void prep_B_kernel(const float* __restrict__ Wd, const float* __restrict__ bd,
                              const float* __restrict__ Wn, const float* __restrict__ bn,
                              const float* __restrict__ Wc, const float* __restrict__ bc,
                              const float* __restrict__ Wt, const float* __restrict__ Win,
                              const float* __restrict__ root, const float* __restrict__ rw,
                              const float* __restrict__ Wo1) {
    int idx = blockIdx.x * 256 + threadIdx.x;
    if (idx >= BTOT + 128) return;
    if (idx >= BTOT) {
        int n = idx - BTOT;
        g_biasU[n] = (n < 64) ? bd[n] : (n < 96) ? bn[n - 64] : bc[n - 96];
        return;
    }
    float v = 0.f;
    if (idx < 16384) {  // featU blockdiag [n,k=128]
        int n = idx >> 7, k = idx & 127;
        if (n < 64) { if (k < 100) v = Wd[n * 100 + k]; }
        else if (n < 96) { if (k >= 100 && k < 106) v = Wn[(n - 64) * 6 + (k - 100)]; }
        else { if (k >= 106 && k < 117) v = Wc[(n - 96) * 11 + (k - 106)]; }
    } else if (idx < 32768) {  // featT
        int l = idx - 16384;
        int n = l >> 7, k = l & 127;
        if (k < 100) v = Wt[n * 100 + k];
    } else if (idx < 49152) {  // lin
        v = Win[idx - 32768];
    } else if (idx < 98304) {  // conv: [n, k=384]: seg0 root^T, seg1/2 rw^T
        int l = idx - 49152;
        int n = l / 384, k = l % 384;
        if (k < 128) v = root[k * 128 + n];
        else if (k < 256) v = rw[(k - 128) * 128 + n];
        else v = rw[16384 + (k - 256) * 128 + n];
    } else {  // o1
        v = Wo1[idx - 98304];
    }
    g_Bh[idx] = __float2half_rn(v);
}

// ======================= CSR build =======================
__global__ void zero2_kernel(int* __restrict__ a, int* __restrict__ b, int n) {
    int i = blockIdx.x * 256 + threadIdx.x;
    if (i < n) { a[i] = 0; b[i] = 0; }
}

__global__ void count_kernel(const int* __restrict__ ei, const int* __restrict__ et,
                             int* __restrict__ cnt) {
    int e = blockIdx.x * 256 + threadIdx.x;
    if (e >= NE) return;
    atomicAdd(&cnt[et[e] * NN + ei[NE + e]], 1);
}

#define SCAN_BS 512
__global__ void scan1_kernel(const int* __restrict__ cnt, int* __restrict__ off,
                             int* __restrict__ bsum, int n) {
    __shared__ int sh[SCAN_BS];
    int t = threadIdx.x;
    int i = blockIdx.x * SCAN_BS + t;
    int v = (i < n) ? cnt[i] : 0;
    sh[t] = v;
    __syncthreads();
#pragma unroll
    for (int d = 1; d < SCAN_BS; d <<= 1) {
        int x = (t >= d) ? sh[t - d] : 0;
        __syncthreads();
        sh[t] += x;
        __syncthreads();
    }
    if (i < n) off[i] = sh[t] - v;  // exclusive within block
    if (t == SCAN_BS - 1) bsum[blockIdx.x] = sh[t];
}

__global__ void scan2_kernel(int* __restrict__ bsum, int nb) {
    __shared__ int sh[1024];
    int t = threadIdx.x;
    int v = (t < nb) ? bsum[t] : 0;
    sh[t] = v;
    __syncthreads();
#pragma unroll
    for (int d = 1; d < 1024; d <<= 1) {
        int x = (t >= d) ? sh[t - d] : 0;
        __syncthreads();
        sh[t] += x;
        __syncthreads();
    }
    if (t < nb) bsum[t] = sh[t] - v;  // exclusive
}

__global__ void scan3_kernel(int* __restrict__ off, const int* __restrict__ bsum, int n) {
    int i = blockIdx.x * SCAN_BS + threadIdx.x;
    if (i < n) off[i] += bsum[blockIdx.x];
}

__global__ void fill_kernel(const int* __restrict__ ei, const int* __restrict__ et,
                            const int* __restrict__ off, int* __restrict__ cur,
                            int* __restrict__ esrc) {
    int e = blockIdx.x * 256 + threadIdx.x;
    if (e >= NE) return;
    int slot = et[e] * NN + ei[NE + e];
    int pos = off[slot] + atomicAdd(&cur[slot], 1);
    esrc[pos] = ei[e];
}

// ======================= CSR gather-mean aggregation =======================
__global__ void agg_kernel(const float* __restrict__ X, const int* __restrict__ off,
                           const int* __restrict__ cnt, const int* __restrict__ esrc,
                           float* __restrict__ Agg) {
    int w = (blockIdx.x * blockDim.x + threadIdx.x) >> 5;
    int lane = threadIdx.x & 31;
    if (w >= NSLOT) return;
    int beg = off[w], deg = cnt[w];
    float4 acc = make_float4(0.f, 0.f, 0.f, 0.f);
    for (int i = 0; i < deg; i++) {
        int src = __ldg(&esrc[beg + i]);
        float4 v = *(const float4*)(X + (size_t)src * 128 + lane * 4);
        acc.x += v.x; acc.y += v.y; acc.z += v.z; acc.w += v.w;
    }
    float s = (deg > 0) ? 1.f / (float)deg : 0.f;
    acc.x *= s; acc.y *= s; acc.z *= s; acc.w *= s;
    *(float4*)(Agg + (size_t)w * 128 + lane * 4) = acc;
}

// ======================= final 128->2 projection =======================
__global__ void out_kernel(const float* __restrict__ X, const float* __restrict__ W2,
                           const float* __restrict__ b2, float* __restrict__ out) {
    int gw = (blockIdx.x * blockDim.x + threadIdx.x) >> 5;
    int lane = threadIdx.x & 31;
    if (gw >= NN) return;
    float4 xv = *(const float4*)(X + (size_t)gw * 128 + lane * 4);
    float4 w0 = *(const float4*)(W2 + lane * 4);
    float4 w1 = *(const float4*)(W2 + 128 + lane * 4);
    float s0 = xv.x * w0.x + xv.y * w0.y + xv.z * w0.z + xv.w * w0.w;
    float s1 = xv.x * w1.x + xv.y * w1.y + xv.z * w1.z + xv.w * w1.w;
#pragma unroll
    for (int off = 16; off; off >>= 1) {
        s0 += __shfl_xor_sync(0xffffffffu, s0, off);
        s1 += __shfl_xor_sync(0xffffffffu, s1, off);
    }
    if (lane == 0) {
        out[(size_t)gw * 2 + 0] = s0 + b2[0];
        out[(size_t)gw * 2 + 1] = s1 + b2[1];
    }
}

// ---------------------------------------------------------------------------
extern "C" void kernel_launch(void* const* d_in, const int* in_sizes, int n_in,
                              void* d_out, int out_size) {
    const float* des   = (const float*)d_in[0];
    const float* tweet = (const float*)d_in[1];
    const float* nump  = (const float*)d_in[2];
    const float* catp  = (const float*)d_in[3];
    const int*   ei    = (const int*)d_in[4];
    const int*   et    = (const int*)d_in[5];
    const float* Wd  = (const float*)d_in[6];  const float* bd  = (const float*)d_in[7];
    const float* Wn  = (const float*)d_in[8];  const float* bn  = (const float*)d_in[9];
    const float* Wc  = (const float*)d_in[10]; const float* bc  = (const float*)d_in[11];
    const float* Wt  = (const float*)d_in[12]; const float* bt  = (const float*)d_in[13];
    const float* Win = (const float*)d_in[14]; const float* bin = (const float*)d_in[15];
    const float* rw    = (const float*)d_in[16];
    const float* rroot = (const float*)d_in[17];
    const float* rbias = (const float*)d_in[18];
    const float* Wo1 = (const float*)d_in[19]; const float* bo1 = (const float*)d_in[20];
    const float* Wo2 = (const float*)d_in[21]; const float* bo2 = (const float*)d_in[22];
    float* out = (float*)d_out;

    float *pA, *pB, *pAgg, *pBiasU;
    int *pCnt, *pOff, *pCur, *pBsum, *pEsrc;
    __half* pBh;
    cudaGetSymbolAddress((void**)&pA, g_bufA);
    cudaGetSymbolAddress((void**)&pB, g_bufB);
    cudaGetSymbolAddress((void**)&pAgg, g_agg);
    cudaGetSymbolAddress((void**)&pCnt, g_cnt);
    cudaGetSymbolAddress((void**)&pOff, g_off);
    cudaGetSymbolAddress((void**)&pCur, g_cur);
    cudaGetSymbolAddress((void**)&pBsum, g_bsum);
    cudaGetSymbolAddress((void**)&pEsrc, g_esrc);
    cudaGetSymbolAddress((void**)&pBh, g_Bh);
    cudaGetSymbolAddress((void**)&pBiasU, g_biasU);

    cudaFuncSetAttribute(mma_gemm<1, 1>, cudaFuncAttributeMaxDynamicSharedMemorySize, GEMM_SMEM);
    cudaFuncSetAttribute(mma_gemm<3, 0>, cudaFuncAttributeMaxDynamicSharedMemorySize, GEMM_SMEM);

    const int GU = (NU + 127) / 128;   // 782
    const int GN = (NN + 127) / 128;   // 1563
    const int SCAN_NB = (NSLOT + SCAN_BS - 1) / SCAN_BS;  // 782 (<=1024)

    // 1-2: pack inputs -> B ; pre-convert weights
    pack_kernel<<<(NN * 128 + 255) / 256, 256>>>(des, tweet, nump, catp, pB);
    prep_B_kernel<<<(BTOT + 128 + 255) / 256, 256>>>(Wd, bd, Wn, bn, Wc, bc, Wt, Win,
                                                     rroot, rw, Wo1);
    // 3-5: feature MLP GEMMs -> A ; x = lrelu(x @ W_in^T + b_in): A -> B
    mma_gemm<1, 1><<<GU, 256, GEMM_SMEM>>>(pB, nullptr, pBh, pBiasU, pA, NU);
    mma_gemm<1, 1><<<GU, 256, GEMM_SMEM>>>(pB + (size_t)NU * 128, nullptr,
                                           pBh + 16384, bt, pA + (size_t)NU * 128, NU);
    mma_gemm<1, 1><<<GN, 256, GEMM_SMEM>>>(pA, nullptr, pBh + 32768, bin, pB, NN);
    // 6-11: CSR build (once; reused by both convs)
    zero2_kernel<<<(NSLOT + 255) / 256, 256>>>(pCnt, pCur, NSLOT);
    count_kernel<<<(NE + 255) / 256, 256>>>(ei, et, pCnt);
    scan1_kernel<<<SCAN_NB, SCAN_BS>>>(pCnt, pOff, pBsum, NSLOT);
    scan2_kernel<<<1, 1024>>>(pBsum, SCAN_NB);
    scan3_kernel<<<SCAN_NB, SCAN_BS>>>(pOff, pBsum, NSLOT);
    fill_kernel<<<(NE + 255) / 256, 256>>>(ei, et, pOff, pCur, pEsrc);

    // conv1: B -> A
    agg_kernel<<<NSLOT / 8, 256>>>(pB, pOff, pCnt, pEsrc, pAgg);
    mma_gemm<3, 0><<<GN, 256, GEMM_SMEM>>>(pB, pAgg, pBh + 49152, rbias, pA, NN);
    // conv2: A -> B
    agg_kernel<<<NSLOT / 8, 256>>>(pA, pOff, pCnt, pEsrc, pAgg);
    mma_gemm<3, 0><<<GN, 256, GEMM_SMEM>>>(pA, pAgg, pBh + 49152, rbias, pB, NN);
    // x = lrelu(x @ W_o1^T + b_o1): B -> A
    mma_gemm<1, 1><<<GN, 256, GEMM_SMEM>>>(pB, nullptr, pBh + 98304, bo1, pA, NN);
    // out = x @ W_o2^T + b_o2
    out_kernel<<<NN / 8, 256>>>(pA, Wo2, bo2, out);
}